// round 1
// baseline (speedup 1.0000x reference)
#include <cuda_runtime.h>
#include <math.h>

#define S_SETS 48
#define M_ITEMS 128
#define DIN 128
#define DM 128
#define H_HEADS 4
#define DH 128
#define L_LAYERS 2
#define ROWS (S_SETS*M_ITEMS)   /* 6144 */
#define HD (H_HEADS*DH)         /* 512  */

#define PA 130   /* a-side smem pitch */
#define PB 129   /* b-side smem pitch */
#define PV 132   /* v-tile smem pitch (float4 aligned) */

// ---------------- device scratch (no allocations allowed) ----------------
__device__ float g_mask[ROWS];
__device__ float g_h[ROWS*DM];
__device__ float g_q[ROWS*HD];
__device__ float g_k[ROWS*HD];
__device__ float g_v[ROWS*HD];
__device__ float g_o[ROWS*HD];
__device__ float g_t[ROWS*DM];
__device__ float g_z[ROWS*HD];
__device__ float g_B[S_SETS*S_SETS*H_HEADS];

__device__ __forceinline__ float gelu_f(float x){
    return 0.5f*x*(1.0f + erff(x*0.70710678118654752440f));
}

__device__ __forceinline__ float block_reduce_sum(float v, float* red){
    int tid = threadIdx.x;
    #pragma unroll
    for (int o=16;o;o>>=1) v += __shfl_xor_sync(0xffffffffu, v, o);
    if ((tid&31)==0) red[tid>>5] = v;
    __syncthreads();
    if (tid < 32) {
        float r = (tid < 8) ? red[tid] : 0.0f;
        #pragma unroll
        for (int o=4;o;o>>=1) r += __shfl_xor_sync(0xffffffffu, r, o);
        if (tid==0) red[0] = r;
    }
    __syncthreads();
    float out = red[0];
    __syncthreads();
    return out;
}

// ---------------- item mask: any(x[row,:] != 0) ----------------
__global__ void mask_kernel(const float* __restrict__ x, float* __restrict__ mask){
    int row = blockIdx.x*8 + (threadIdx.x>>5);
    int lane = threadIdx.x & 31;
    float4 v = reinterpret_cast<const float4*>(x + (long)row*DIN)[lane];
    bool nz = (v.x!=0.0f)||(v.y!=0.0f)||(v.z!=0.0f)||(v.w!=0.0f);
    unsigned b = __ballot_sync(0xffffffffu, nz);
    if (lane==0) mask[row] = b ? 1.0f : 0.0f;
}

// ---------------- generic tiled SGEMM: C[6144,N] = A[6144,K] @ B[K,N] ----------------
// epi: 0 = none, 1 = gelu(c)*mask[row]
__global__ __launch_bounds__(256) void gemm_nn(
    const float* __restrict__ A, const float* __restrict__ B, float* __restrict__ C,
    int N, int K, int epi, const float* __restrict__ mask)
{
    __shared__ float As[16*65];
    __shared__ float Bs[16*64];
    int tid = threadIdx.x;
    int tx = tid & 15, ty = tid >> 4;
    int row0 = blockIdx.y*64, col0 = blockIdx.x*64;
    float acc[4][4] = {};
    for (int k0=0;k0<K;k0+=16){
        #pragma unroll 4
        for (int i=tid;i<64*16;i+=256){
            int m = i>>4, kk = i&15;
            As[kk*65+m] = A[(long)(row0+m)*K + k0+kk];
        }
        #pragma unroll 4
        for (int i=tid;i<16*64;i+=256){
            int kk = i>>6, n = i&63;
            Bs[kk*64+n] = B[(long)(k0+kk)*N + col0+n];
        }
        __syncthreads();
        #pragma unroll
        for (int kk=0;kk<16;kk++){
            float a0 = As[kk*65 + ty*4 + 0];
            float a1 = As[kk*65 + ty*4 + 1];
            float a2 = As[kk*65 + ty*4 + 2];
            float a3 = As[kk*65 + ty*4 + 3];
            float4 b = *(const float4*)(Bs + kk*64 + tx*4);
            acc[0][0] += a0*b.x; acc[0][1] += a0*b.y; acc[0][2] += a0*b.z; acc[0][3] += a0*b.w;
            acc[1][0] += a1*b.x; acc[1][1] += a1*b.y; acc[1][2] += a1*b.z; acc[1][3] += a1*b.w;
            acc[2][0] += a2*b.x; acc[2][1] += a2*b.y; acc[2][2] += a2*b.z; acc[2][3] += a2*b.w;
            acc[3][0] += a3*b.x; acc[3][1] += a3*b.y; acc[3][2] += a3*b.z; acc[3][3] += a3*b.w;
        }
        __syncthreads();
    }
    #pragma unroll
    for (int i=0;i<4;i++){
        int r = row0 + ty*4 + i;
        float mrow = (epi==1) ? mask[r] : 1.0f;
        #pragma unroll
        for (int j=0;j<4;j++){
            float vv = acc[i][j];
            if (epi==1) vv = gelu_f(vv)*mrow;
            C[(long)r*N + col0 + tx*4 + j] = vv;
        }
    }
}

// ---------------- fused attention per (head, set): S = QK^T/sqrt(DH), masked softmax, O = A V ----------------
__global__ __launch_bounds__(256) void attn_kernel(
    const float* __restrict__ q, const float* __restrict__ k,
    const float* __restrict__ v, float* __restrict__ o)
{
    int h = blockIdx.x, s = blockIdx.y;
    extern __shared__ float sm[];
    float* qs = sm;                          // [128][PA], reused for scores/probs
    float* ks = sm + 128*PA;                 // [128][PB]
    float* vs = sm + 128*PA + 128*PB;        // [128][PV]
    int tid = threadIdx.x;
    long base = (long)(s*M_ITEMS)*HD + h*DH;

    for (int idx=tid; idx<128*32; idx+=256){
        int m = idx>>5, dg = idx&31;
        float4 a = *(const float4*)(q + base + (long)m*HD + dg*4);
        float4 b = *(const float4*)(k + base + (long)m*HD + dg*4);
        float4 c = *(const float4*)(v + base + (long)m*HD + dg*4);
        float* pq = qs + m*PA + dg*4; pq[0]=a.x; pq[1]=a.y; pq[2]=a.z; pq[3]=a.w;
        float* pk = ks + m*PB + dg*4; pk[0]=b.x; pk[1]=b.y; pk[2]=b.z; pk[3]=b.w;
        float* pv = vs + m*PV + dg*4; pv[0]=c.x; pv[1]=c.y; pv[2]=c.z; pv[3]=c.w;
    }
    __syncthreads();

    int tx = tid&15, ty = tid>>4;
    int m0 = ty*8, n0 = tx*8;
    float acc[8][8] = {};
    for (int d=0; d<128; d++){
        float af[8], bf[8];
        #pragma unroll
        for (int i=0;i<8;i++) af[i] = qs[(m0+i)*PA + d];
        #pragma unroll
        for (int j=0;j<8;j++) bf[j] = ks[(n0+j)*PB + d];
        #pragma unroll
        for (int i=0;i<8;i++)
            #pragma unroll
            for (int j=0;j<8;j++) acc[i][j] += af[i]*bf[j];
    }
    __syncthreads();
    const float scale = 0.08838834764831844f;  // 1/sqrt(128)
    #pragma unroll
    for (int i=0;i<8;i++)
        #pragma unroll
        for (int j=0;j<8;j++) qs[(m0+i)*PA + n0+j] = acc[i][j]*scale;
    __syncthreads();

    // masked softmax per row: mask = (s != 0); max over ALL values (reference semantics)
    int warp = tid>>5, lane = tid&31;
    for (int m=warp; m<128; m+=8){
        float* row = qs + m*PA;
        float vals[4]; float mx = -INFINITY;
        #pragma unroll
        for (int r=0;r<4;r++){ vals[r] = row[lane+32*r]; mx = fmaxf(mx, vals[r]); }
        #pragma unroll
        for (int off=16;off;off>>=1) mx = fmaxf(mx, __shfl_xor_sync(0xffffffffu, mx, off));
        float sum = 0.0f;
        #pragma unroll
        for (int r=0;r<4;r++){
            float e = (vals[r]!=0.0f) ? expf(vals[r]-mx) : 0.0f;
            vals[r] = e; sum += e;
        }
        #pragma unroll
        for (int off=16;off;off>>=1) sum += __shfl_xor_sync(0xffffffffu, sum, off);
        float inv = 1.0f/(sum + 1e-10f);
        #pragma unroll
        for (int r=0;r<4;r++) row[lane+32*r] = vals[r]*inv;
    }
    __syncthreads();

    float acc2[8][8] = {};
    for (int n=0;n<128;n++){
        float af[8];
        #pragma unroll
        for (int i=0;i<8;i++) af[i] = qs[(m0+i)*PA + n];
        float4 b0 = *(const float4*)(vs + n*PV + n0);
        float4 b1 = *(const float4*)(vs + n*PV + n0 + 4);
        #pragma unroll
        for (int i=0;i<8;i++){
            acc2[i][0] += af[i]*b0.x; acc2[i][1] += af[i]*b0.y;
            acc2[i][2] += af[i]*b0.z; acc2[i][3] += af[i]*b0.w;
            acc2[i][4] += af[i]*b1.x; acc2[i][5] += af[i]*b1.y;
            acc2[i][6] += af[i]*b1.z; acc2[i][7] += af[i]*b1.w;
        }
    }
    #pragma unroll
    for (int i=0;i<8;i++)
        #pragma unroll
        for (int j=0;j<8;j++)
            o[base + (long)(m0+i)*HD + n0 + j] = acc2[i][j];
}

// ---------------- set_norm fused with residual add (+ optional gelu on the added branch) ----------------
__global__ __launch_bounds__(256) void setnorm_kernel(
    float* __restrict__ hbuf, const float* __restrict__ abuf,
    const float* __restrict__ mitem, const int* __restrict__ x_size,
    int apply_gelu)
{
    int s = blockIdx.x;
    extern __shared__ float sm[];
    float* ts = sm;              // [128][130]
    float* rs = sm + 128*130;    // [128] row sums
    __shared__ float red[32];
    int tid = threadIdx.x;
    long base = (long)s*M_ITEMS*DM;

    for (int idx=tid; idx<128*32; idx+=256){
        int m = idx>>5, dg = idx&31;
        float mrow = mitem[s*M_ITEMS+m];
        float4 hv = *(const float4*)(hbuf + base + (long)m*DM + dg*4);
        float4 av = *(const float4*)(abuf + base + (long)m*DM + dg*4);
        float a0 = apply_gelu ? gelu_f(av.x) : av.x;
        float a1 = apply_gelu ? gelu_f(av.y) : av.y;
        float a2 = apply_gelu ? gelu_f(av.z) : av.z;
        float a3 = apply_gelu ? gelu_f(av.w) : av.w;
        float* pt = ts + m*130 + dg*4;
        pt[0] = hv.x + a0*mrow; pt[1] = hv.y + a1*mrow;
        pt[2] = hv.z + a2*mrow; pt[3] = hv.w + a3*mrow;
    }
    __syncthreads();

    int warp = tid>>5, lane = tid&31;
    for (int m=warp; m<128; m+=8){
        float v = ts[m*130+lane] + ts[m*130+lane+32] + ts[m*130+lane+64] + ts[m*130+lane+96];
        #pragma unroll
        for (int off=16;off;off>>=1) v += __shfl_xor_sync(0xffffffffu, v, off);
        if (lane==0) rs[m] = v;
    }
    __syncthreads();

    float tv = (tid<128) ? rs[tid] : 0.0f;
    float total = block_reduce_sum(tv, red);
    int szi = x_size[s]; if (szi < 1) szi = 1;
    float denom = (float)szi * 128.0f;
    float mean = total / denom;

    float vv = 0.0f;
    for (int idx=tid; idx<128*32; idx+=256){
        int m = idx>>5, dg = idx&31;
        if (rs[m] != 0.0f){
            float* pt = ts + m*130 + dg*4;
            float d0 = pt[0]-mean, d1 = pt[1]-mean, d2 = pt[2]-mean, d3 = pt[3]-mean;
            vv += d0*d0 + d1*d1 + d2*d2 + d3*d3;
        }
    }
    float vart = block_reduce_sum(vv, red);
    float inv = 1.0f/(sqrtf(vart/denom) + 1e-8f);

    for (int idx=tid; idx<128*32; idx+=256){
        int m = idx>>5, dg = idx&31;
        float mr = (rs[m] != 0.0f) ? 1.0f : 0.0f;
        float* pt = ts + m*130 + dg*4;
        float4 outv;
        outv.x = (pt[0]-mean)*inv*mr;
        outv.y = (pt[1]-mean)*inv*mr;
        outv.z = (pt[2]-mean)*inv*mr;
        outv.w = (pt[3]-mean)*inv*mr;
        *(float4*)(hbuf + base + (long)m*DM + dg*4) = outv;
    }
}

// ---------------- cross-set Gram: B[j,i,h] = sum_{m,n} leaky(z_j·z_i / sqrt(DH)); symmetric j<=i ----------------
__global__ __launch_bounds__(256) void gram_kernel(const float* __restrict__ z, float* __restrict__ Bout)
{
    int h = blockIdx.y;
    int p = blockIdx.x;
    int j = 0, rem = p;
    while (rem >= S_SETS - j){ rem -= S_SETS - j; j++; }
    int i = j + rem;

    extern __shared__ float sm[];
    float* zj = sm;              // [128][PA]
    float* zi = sm + 128*PA;     // [128][PB]
    __shared__ float red[32];
    int tid = threadIdx.x;
    long basej = (long)(j*M_ITEMS)*HD + h*DH;
    long basei = (long)(i*M_ITEMS)*HD + h*DH;

    for (int idx=tid; idx<128*32; idx+=256){
        int m = idx>>5, dg = idx&31;
        float4 a = *(const float4*)(z + basej + (long)m*HD + dg*4);
        float4 b = *(const float4*)(z + basei + (long)m*HD + dg*4);
        float* pa = zj + m*PA + dg*4; pa[0]=a.x; pa[1]=a.y; pa[2]=a.z; pa[3]=a.w;
        float* pb = zi + m*PB + dg*4; pb[0]=b.x; pb[1]=b.y; pb[2]=b.z; pb[3]=b.w;
    }
    __syncthreads();

    int tx = tid&15, ty = tid>>4;
    int m0 = ty*8, n0 = tx*8;
    float acc[8][8] = {};
    for (int d=0; d<128; d++){
        float af[8], bf[8];
        #pragma unroll
        for (int ii=0;ii<8;ii++) af[ii] = zj[(m0+ii)*PA + d];
        #pragma unroll
        for (int jj=0;jj<8;jj++) bf[jj] = zi[(n0+jj)*PB + d];
        #pragma unroll
        for (int ii=0;ii<8;ii++)
            #pragma unroll
            for (int jj=0;jj<8;jj++) acc[ii][jj] += af[ii]*bf[jj];
    }
    const float scale = 0.08838834764831844f;
    float lsum = 0.0f;
    #pragma unroll
    for (int ii=0;ii<8;ii++)
        #pragma unroll
        for (int jj=0;jj<8;jj++){
            float vv = acc[ii][jj]*scale;
            lsum += (vv >= 0.0f) ? vv : 0.3f*vv;
        }
    float total = block_reduce_sum(lsum, red);
    if (tid==0){
        Bout[(j*S_SETS+i)*H_HEADS + h] = total;
        Bout[(i*S_SETS+j)*H_HEADS + h] = total;
    }
}

// ---------------- finalize: out[j,i] = sum_h B[j,i,h]*w2[h] / size[i] / M ----------------
__global__ void final_kernel(const float* __restrict__ Bm, const int* __restrict__ x_size,
                             const float* __restrict__ w2, float* __restrict__ out)
{
    int idx = blockIdx.x*256 + threadIdx.x;
    if (idx >= S_SETS*S_SETS) return;
    int j = idx / S_SETS, i = idx % S_SETS;
    int szi = x_size[i]; if (szi < 1) szi = 1;
    float acc = 0.0f;
    #pragma unroll
    for (int h=0; h<H_HEADS; h++) acc += Bm[(j*S_SETS+i)*H_HEADS + h] * w2[h];
    out[idx] = acc / (float)szi / (float)M_ITEMS;
}

// ---------------- launch ----------------
extern "C" void kernel_launch(void* const* d_in, const int* in_sizes, int n_in,
                              void* d_out, int out_size)
{
    const float* x      = (const float*)d_in[0];
    const int*   x_size = (const int*)  d_in[1];
    const float* W_proj = (const float*)d_in[2];
    const float* Wq     = (const float*)d_in[3];
    const float* Wk     = (const float*)d_in[4];
    const float* Wv     = (const float*)d_in[5];
    const float* Wh     = (const float*)d_in[6];
    const float* Wfc    = (const float*)d_in[7];
    const float* Wc     = (const float*)d_in[8];
    const float* w2     = (const float*)d_in[9];
    float* out = (float*)d_out;

    float *pm, *ph, *pq, *pk, *pv, *po, *pt, *pz, *pB;
    cudaGetSymbolAddress((void**)&pm, g_mask);
    cudaGetSymbolAddress((void**)&ph, g_h);
    cudaGetSymbolAddress((void**)&pq, g_q);
    cudaGetSymbolAddress((void**)&pk, g_k);
    cudaGetSymbolAddress((void**)&pv, g_v);
    cudaGetSymbolAddress((void**)&po, g_o);
    cudaGetSymbolAddress((void**)&pt, g_t);
    cudaGetSymbolAddress((void**)&pz, g_z);
    cudaGetSymbolAddress((void**)&pB, g_B);

    const int ATTN_SMEM = 128*(PA+PB+PV)*4;     // 200192 B
    const int GRAM_SMEM = 128*(PA+PB)*4;        // 132608 B
    const int SN_SMEM   = 128*130*4 + 128*4;    //  67072 B
    cudaFuncSetAttribute(attn_kernel,    cudaFuncAttributeMaxDynamicSharedMemorySize, ATTN_SMEM);
    cudaFuncSetAttribute(gram_kernel,    cudaFuncAttributeMaxDynamicSharedMemorySize, GRAM_SMEM);
    cudaFuncSetAttribute(setnorm_kernel, cudaFuncAttributeMaxDynamicSharedMemorySize, SN_SMEM);

    mask_kernel<<<ROWS/8, 256>>>(x, pm);
    // h = gelu(x @ W_proj) * mask
    gemm_nn<<<dim3(DM/64, ROWS/64), 256>>>(x, W_proj, ph, DM, DIN, 1, pm);

    for (int l=0; l<L_LAYERS; l++){
        gemm_nn<<<dim3(HD/64, ROWS/64), 256>>>(ph, Wq + (long)l*DM*HD, pq, HD, DM, 0, nullptr);
        gemm_nn<<<dim3(HD/64, ROWS/64), 256>>>(ph, Wk + (long)l*DM*HD, pk, HD, DM, 0, nullptr);
        gemm_nn<<<dim3(HD/64, ROWS/64), 256>>>(ph, Wv + (long)l*DM*HD, pv, HD, DM, 0, nullptr);
        attn_kernel<<<dim3(H_HEADS, S_SETS), 256, ATTN_SMEM>>>(pq, pk, pv, po);
        gemm_nn<<<dim3(DM/64, ROWS/64), 256>>>(po, Wh + (long)l*HD*DM, pt, DM, HD, 0, nullptr);
        setnorm_kernel<<<S_SETS, 256, SN_SMEM>>>(ph, pt, pm, x_size, 0);
        gemm_nn<<<dim3(DM/64, ROWS/64), 256>>>(ph, Wfc + (long)l*DM*DM, pt, DM, DM, 0, nullptr);
        setnorm_kernel<<<S_SETS, 256, SN_SMEM>>>(ph, pt, pm, x_size, 1);
    }

    gemm_nn<<<dim3(HD/64, ROWS/64), 256>>>(ph, Wc, pz, HD, DM, 0, nullptr);
    gram_kernel<<<dim3(S_SETS*(S_SETS+1)/2, H_HEADS), 256, GRAM_SMEM>>>(pz, pB);
    final_kernel<<<(S_SETS*S_SETS + 255)/256, 256>>>(pB, x_size, w2, out);
}

// round 2
// speedup vs baseline: 1.3720x; 1.3720x over previous
#include <cuda_runtime.h>
#include <math.h>
#include <mma.h>

using namespace nvcuda;

#define S_SETS 48
#define M_ITEMS 128
#define DIN 128
#define DM 128
#define H_HEADS 4
#define DH 128
#define L_LAYERS 2
#define ROWS (S_SETS*M_ITEMS)   /* 6144 */
#define HD (H_HEADS*DH)         /* 512  */

#define PA 130   /* a-side smem pitch (attn) */
#define PB 129   /* b-side smem pitch (attn) */
#define PV 132   /* v-tile smem pitch (float4 aligned) */
#define PG 136   /* gram wmma smem pitch (floats, 16B-multiple) */

// ---------------- device scratch (no allocations allowed) ----------------
__device__ float g_mask[ROWS];
__device__ float g_h[ROWS*DM];
__device__ float g_q[ROWS*HD];
__device__ float g_k[ROWS*HD];
__device__ float g_v[ROWS*HD];
__device__ float g_o[ROWS*HD];
__device__ float g_t[ROWS*DM];
__device__ float g_z[ROWS*HD];
__device__ float g_B[S_SETS*S_SETS*H_HEADS];

__device__ __forceinline__ float gelu_f(float x){
    return 0.5f*x*(1.0f + erff(x*0.70710678118654752440f));
}

__device__ __forceinline__ float block_reduce_sum(float v, float* red){
    int tid = threadIdx.x;
    #pragma unroll
    for (int o=16;o;o>>=1) v += __shfl_xor_sync(0xffffffffu, v, o);
    if ((tid&31)==0) red[tid>>5] = v;
    __syncthreads();
    if (tid < 32) {
        float r = (tid < 8) ? red[tid] : 0.0f;
        #pragma unroll
        for (int o=4;o;o>>=1) r += __shfl_xor_sync(0xffffffffu, r, o);
        if (tid==0) red[0] = r;
    }
    __syncthreads();
    float out = red[0];
    __syncthreads();
    return out;
}

// ---------------- item mask: any(x[row,:] != 0) ----------------
__global__ void mask_kernel(const float* __restrict__ x, float* __restrict__ mask){
    int row = blockIdx.x*8 + (threadIdx.x>>5);
    int lane = threadIdx.x & 31;
    float4 v = reinterpret_cast<const float4*>(x + (long)row*DIN)[lane];
    bool nz = (v.x!=0.0f)||(v.y!=0.0f)||(v.z!=0.0f)||(v.w!=0.0f);
    unsigned b = __ballot_sync(0xffffffffu, nz);
    if (lane==0) mask[row] = b ? 1.0f : 0.0f;
}

// ---------------- generic tiled SGEMM: C[6144,N] = A[6144,K] @ B[K,N] ----------------
// epi: 0 = none, 1 = gelu(c)*mask[row]
__global__ __launch_bounds__(256) void gemm_nn(
    const float* __restrict__ A, const float* __restrict__ B, float* __restrict__ C,
    int N, int K, int epi, const float* __restrict__ mask)
{
    __shared__ float As[16*65];
    __shared__ float Bs[16*64];
    int tid = threadIdx.x;
    int tx = tid & 15, ty = tid >> 4;
    int row0 = blockIdx.y*64, col0 = blockIdx.x*64;
    float acc[4][4] = {};
    for (int k0=0;k0<K;k0+=16){
        #pragma unroll 4
        for (int i=tid;i<64*16;i+=256){
            int m = i>>4, kk = i&15;
            As[kk*65+m] = A[(long)(row0+m)*K + k0+kk];
        }
        #pragma unroll 4
        for (int i=tid;i<16*64;i+=256){
            int kk = i>>6, n = i&63;
            Bs[kk*64+n] = B[(long)(k0+kk)*N + col0+n];
        }
        __syncthreads();
        #pragma unroll
        for (int kk=0;kk<16;kk++){
            float a0 = As[kk*65 + ty*4 + 0];
            float a1 = As[kk*65 + ty*4 + 1];
            float a2 = As[kk*65 + ty*4 + 2];
            float a3 = As[kk*65 + ty*4 + 3];
            float4 b = *(const float4*)(Bs + kk*64 + tx*4);
            acc[0][0] += a0*b.x; acc[0][1] += a0*b.y; acc[0][2] += a0*b.z; acc[0][3] += a0*b.w;
            acc[1][0] += a1*b.x; acc[1][1] += a1*b.y; acc[1][2] += a1*b.z; acc[1][3] += a1*b.w;
            acc[2][0] += a2*b.x; acc[2][1] += a2*b.y; acc[2][2] += a2*b.z; acc[2][3] += a2*b.w;
            acc[3][0] += a3*b.x; acc[3][1] += a3*b.y; acc[3][2] += a3*b.z; acc[3][3] += a3*b.w;
        }
        __syncthreads();
    }
    #pragma unroll
    for (int i=0;i<4;i++){
        int r = row0 + ty*4 + i;
        float mrow = (epi==1) ? mask[r] : 1.0f;
        #pragma unroll
        for (int j=0;j<4;j++){
            float vv = acc[i][j];
            if (epi==1) vv = gelu_f(vv)*mrow;
            C[(long)r*N + col0 + tx*4 + j] = vv;
        }
    }
}

// ---------------- fused attention per (head, set) ----------------
__global__ __launch_bounds__(256) void attn_kernel(
    const float* __restrict__ q, const float* __restrict__ k,
    const float* __restrict__ v, float* __restrict__ o)
{
    int h = blockIdx.x, s = blockIdx.y;
    extern __shared__ float sm[];
    float* qs = sm;                          // [128][PA], reused for scores/probs
    float* ks = sm + 128*PA;                 // [128][PB]
    float* vs = sm + 128*PA + 128*PB;        // [128][PV]
    int tid = threadIdx.x;
    long base = (long)(s*M_ITEMS)*HD + h*DH;

    for (int idx=tid; idx<128*32; idx+=256){
        int m = idx>>5, dg = idx&31;
        float4 a = *(const float4*)(q + base + (long)m*HD + dg*4);
        float4 b = *(const float4*)(k + base + (long)m*HD + dg*4);
        float4 c = *(const float4*)(v + base + (long)m*HD + dg*4);
        float* pq = qs + m*PA + dg*4; pq[0]=a.x; pq[1]=a.y; pq[2]=a.z; pq[3]=a.w;
        float* pk = ks + m*PB + dg*4; pk[0]=b.x; pk[1]=b.y; pk[2]=b.z; pk[3]=b.w;
        float* pv = vs + m*PV + dg*4; pv[0]=c.x; pv[1]=c.y; pv[2]=c.z; pv[3]=c.w;
    }
    __syncthreads();

    int tx = tid&15, ty = tid>>4;
    int m0 = ty*8, n0 = tx*8;
    float acc[8][8] = {};
    for (int d=0; d<128; d++){
        float af[8], bf[8];
        #pragma unroll
        for (int i=0;i<8;i++) af[i] = qs[(m0+i)*PA + d];
        #pragma unroll
        for (int j=0;j<8;j++) bf[j] = ks[(n0+j)*PB + d];
        #pragma unroll
        for (int i=0;i<8;i++)
            #pragma unroll
            for (int j=0;j<8;j++) acc[i][j] += af[i]*bf[j];
    }
    __syncthreads();
    const float scale = 0.08838834764831844f;  // 1/sqrt(128)
    #pragma unroll
    for (int i=0;i<8;i++)
        #pragma unroll
        for (int j=0;j<8;j++) qs[(m0+i)*PA + n0+j] = acc[i][j]*scale;
    __syncthreads();

    int warp = tid>>5, lane = tid&31;
    for (int m=warp; m<128; m+=8){
        float* row = qs + m*PA;
        float vals[4]; float mx = -INFINITY;
        #pragma unroll
        for (int r=0;r<4;r++){ vals[r] = row[lane+32*r]; mx = fmaxf(mx, vals[r]); }
        #pragma unroll
        for (int off=16;off;off>>=1) mx = fmaxf(mx, __shfl_xor_sync(0xffffffffu, mx, off));
        float sum = 0.0f;
        #pragma unroll
        for (int r=0;r<4;r++){
            float e = (vals[r]!=0.0f) ? expf(vals[r]-mx) : 0.0f;
            vals[r] = e; sum += e;
        }
        #pragma unroll
        for (int off=16;off;off>>=1) sum += __shfl_xor_sync(0xffffffffu, sum, off);
        float inv = 1.0f/(sum + 1e-10f);
        #pragma unroll
        for (int r=0;r<4;r++) row[lane+32*r] = vals[r]*inv;
    }
    __syncthreads();

    float acc2[8][8] = {};
    for (int n=0;n<128;n++){
        float af[8];
        #pragma unroll
        for (int i=0;i<8;i++) af[i] = qs[(m0+i)*PA + n];
        float4 b0 = *(const float4*)(vs + n*PV + n0);
        float4 b1 = *(const float4*)(vs + n*PV + n0 + 4);
        #pragma unroll
        for (int i=0;i<8;i++){
            acc2[i][0] += af[i]*b0.x; acc2[i][1] += af[i]*b0.y;
            acc2[i][2] += af[i]*b0.z; acc2[i][3] += af[i]*b0.w;
            acc2[i][4] += af[i]*b1.x; acc2[i][5] += af[i]*b1.y;
            acc2[i][6] += af[i]*b1.z; acc2[i][7] += af[i]*b1.w;
        }
    }
    #pragma unroll
    for (int i=0;i<8;i++)
        #pragma unroll
        for (int j=0;j<8;j++)
            o[base + (long)(m0+i)*HD + n0 + j] = acc2[i][j];
}

// ---------------- set_norm fused with residual add (+ optional gelu) ----------------
__global__ __launch_bounds__(256) void setnorm_kernel(
    float* __restrict__ hbuf, const float* __restrict__ abuf,
    const float* __restrict__ mitem, const int* __restrict__ x_size,
    int apply_gelu)
{
    int s = blockIdx.x;
    extern __shared__ float sm[];
    float* ts = sm;              // [128][130]
    float* rs = sm + 128*130;    // [128] row sums
    __shared__ float red[32];
    int tid = threadIdx.x;
    long base = (long)s*M_ITEMS*DM;

    for (int idx=tid; idx<128*32; idx+=256){
        int m = idx>>5, dg = idx&31;
        float mrow = mitem[s*M_ITEMS+m];
        float4 hv = *(const float4*)(hbuf + base + (long)m*DM + dg*4);
        float4 av = *(const float4*)(abuf + base + (long)m*DM + dg*4);
        float a0 = apply_gelu ? gelu_f(av.x) : av.x;
        float a1 = apply_gelu ? gelu_f(av.y) : av.y;
        float a2 = apply_gelu ? gelu_f(av.z) : av.z;
        float a3 = apply_gelu ? gelu_f(av.w) : av.w;
        float* pt = ts + m*130 + dg*4;
        pt[0] = hv.x + a0*mrow; pt[1] = hv.y + a1*mrow;
        pt[2] = hv.z + a2*mrow; pt[3] = hv.w + a3*mrow;
    }
    __syncthreads();

    int warp = tid>>5, lane = tid&31;
    for (int m=warp; m<128; m+=8){
        float v = ts[m*130+lane] + ts[m*130+lane+32] + ts[m*130+lane+64] + ts[m*130+lane+96];
        #pragma unroll
        for (int off=16;off;off>>=1) v += __shfl_xor_sync(0xffffffffu, v, off);
        if (lane==0) rs[m] = v;
    }
    __syncthreads();

    float tv = (tid<128) ? rs[tid] : 0.0f;
    float total = block_reduce_sum(tv, red);
    int szi = x_size[s]; if (szi < 1) szi = 1;
    float denom = (float)szi * 128.0f;
    float mean = total / denom;

    float vv = 0.0f;
    for (int idx=tid; idx<128*32; idx+=256){
        int m = idx>>5, dg = idx&31;
        if (rs[m] != 0.0f){
            float* pt = ts + m*130 + dg*4;
            float d0 = pt[0]-mean, d1 = pt[1]-mean, d2 = pt[2]-mean, d3 = pt[3]-mean;
            vv += d0*d0 + d1*d1 + d2*d2 + d3*d3;
        }
    }
    float vart = block_reduce_sum(vv, red);
    float inv = 1.0f/(sqrtf(vart/denom) + 1e-8f);

    for (int idx=tid; idx<128*32; idx+=256){
        int m = idx>>5, dg = idx&31;
        float mr = (rs[m] != 0.0f) ? 1.0f : 0.0f;
        float* pt = ts + m*130 + dg*4;
        float4 outv;
        outv.x = (pt[0]-mean)*inv*mr;
        outv.y = (pt[1]-mean)*inv*mr;
        outv.z = (pt[2]-mean)*inv*mr;
        outv.w = (pt[3]-mean)*inv*mr;
        *(float4*)(hbuf + base + (long)m*DM + dg*4) = outv;
    }
}

// ---------------- cross-set Gram via WMMA tf32 ----------------
// B[j,i,h] = sum_{m,n} leaky( (z_j @ z_i^T)/sqrt(DH) ); symmetric over (j,i).
// One block per (pair p, head h). 8 warps; warp w owns rows [16w,16w+16).
// Loop k outer with 8 live accumulator fragments (one per 16-wide n tile):
// A fragment loaded once per k-step, B 8x per k-step.
__global__ __launch_bounds__(256) void gram_wmma_kernel(
    const float* __restrict__ z, float* __restrict__ Bout)
{
    int h = blockIdx.y;
    int p = blockIdx.x;
    int j = 0, rem = p;
    while (rem >= S_SETS - j){ rem -= S_SETS - j; j++; }
    int i = j + rem;

    extern __shared__ float sm[];
    float* zj = sm;              // [128][PG]  (A, row-major m x k)
    float* zi = sm + 128*PG;     // [128][PG]  (B as col-major k x n: element (k,n) at zi[n*PG+k])
    __shared__ float red[32];
    int tid = threadIdx.x;
    int warp = tid >> 5;
    long basej = (long)(j*M_ITEMS)*HD + h*DH;
    long basei = (long)(i*M_ITEMS)*HD + h*DH;

    // stage with tf32 rounding
    for (int idx=tid; idx<128*32; idx+=256){
        int m = idx>>5, dg = idx&31;
        float4 a = *(const float4*)(z + basej + (long)m*HD + dg*4);
        float4 b = *(const float4*)(z + basei + (long)m*HD + dg*4);
        float* pa = zj + m*PG + dg*4;
        pa[0]=wmma::__float_to_tf32(a.x); pa[1]=wmma::__float_to_tf32(a.y);
        pa[2]=wmma::__float_to_tf32(a.z); pa[3]=wmma::__float_to_tf32(a.w);
        float* pb = zi + m*PG + dg*4;
        pb[0]=wmma::__float_to_tf32(b.x); pb[1]=wmma::__float_to_tf32(b.y);
        pb[2]=wmma::__float_to_tf32(b.z); pb[3]=wmma::__float_to_tf32(b.w);
    }
    __syncthreads();

    wmma::fragment<wmma::accumulator, 16, 16, 8, float> acc[8];
    #pragma unroll
    for (int t=0;t<8;t++) wmma::fill_fragment(acc[t], 0.0f);

    int m0 = warp*16;
    #pragma unroll
    for (int k0=0; k0<128; k0+=8){
        wmma::fragment<wmma::matrix_a, 16, 16, 8, wmma::precision::tf32, wmma::row_major> afrag;
        wmma::load_matrix_sync(afrag, zj + m0*PG + k0, PG);
        #pragma unroll
        for (int t=0;t<8;t++){
            wmma::fragment<wmma::matrix_b, 16, 16, 8, wmma::precision::tf32, wmma::col_major> bfrag;
            wmma::load_matrix_sync(bfrag, zi + (t*16)*PG + k0, PG);
            wmma::mma_sync(acc[t], afrag, bfrag, acc[t]);
        }
    }

    const float scale = 0.08838834764831844f;  // 1/sqrt(128)
    float lsum = 0.0f;
    #pragma unroll
    for (int t=0;t<8;t++)
        #pragma unroll
        for (int e=0;e<acc[t].num_elements;e++){
            float vv = acc[t].x[e]*scale;
            lsum += (vv >= 0.0f) ? vv : 0.3f*vv;
        }
    float total = block_reduce_sum(lsum, red);
    if (tid==0){
        Bout[(j*S_SETS+i)*H_HEADS + h] = total;
        Bout[(i*S_SETS+j)*H_HEADS + h] = total;
    }
}

// ---------------- finalize: out[j,i] = sum_h B[j,i,h]*w2[h] / size[i] / M ----------------
__global__ void final_kernel(const float* __restrict__ Bm, const int* __restrict__ x_size,
                             const float* __restrict__ w2, float* __restrict__ out)
{
    int idx = blockIdx.x*256 + threadIdx.x;
    if (idx >= S_SETS*S_SETS) return;
    int j = idx / S_SETS, i = idx % S_SETS;
    int szi = x_size[i]; if (szi < 1) szi = 1;
    float acc = 0.0f;
    #pragma unroll
    for (int h=0; h<H_HEADS; h++) acc += Bm[(j*S_SETS+i)*H_HEADS + h] * w2[h];
    out[idx] = acc / (float)szi / (float)M_ITEMS;
}

// ---------------- launch ----------------
extern "C" void kernel_launch(void* const* d_in, const int* in_sizes, int n_in,
                              void* d_out, int out_size)
{
    const float* x      = (const float*)d_in[0];
    const int*   x_size = (const int*)  d_in[1];
    const float* W_proj = (const float*)d_in[2];
    const float* Wq     = (const float*)d_in[3];
    const float* Wk     = (const float*)d_in[4];
    const float* Wv     = (const float*)d_in[5];
    const float* Wh     = (const float*)d_in[6];
    const float* Wfc    = (const float*)d_in[7];
    const float* Wc     = (const float*)d_in[8];
    const float* w2     = (const float*)d_in[9];
    float* out = (float*)d_out;

    float *pm, *ph, *pq, *pk, *pv, *po, *pt, *pz, *pB;
    cudaGetSymbolAddress((void**)&pm, g_mask);
    cudaGetSymbolAddress((void**)&ph, g_h);
    cudaGetSymbolAddress((void**)&pq, g_q);
    cudaGetSymbolAddress((void**)&pk, g_k);
    cudaGetSymbolAddress((void**)&pv, g_v);
    cudaGetSymbolAddress((void**)&po, g_o);
    cudaGetSymbolAddress((void**)&pt, g_t);
    cudaGetSymbolAddress((void**)&pz, g_z);
    cudaGetSymbolAddress((void**)&pB, g_B);

    const int ATTN_SMEM = 128*(PA+PB+PV)*4;     // 200192 B
    const int GRAM_SMEM = 2*128*PG*4;           // 139264 B
    const int SN_SMEM   = 128*130*4 + 128*4;    //  67072 B
    cudaFuncSetAttribute(attn_kernel,      cudaFuncAttributeMaxDynamicSharedMemorySize, ATTN_SMEM);
    cudaFuncSetAttribute(gram_wmma_kernel, cudaFuncAttributeMaxDynamicSharedMemorySize, GRAM_SMEM);
    cudaFuncSetAttribute(setnorm_kernel,   cudaFuncAttributeMaxDynamicSharedMemorySize, SN_SMEM);

    mask_kernel<<<ROWS/8, 256>>>(x, pm);
    gemm_nn<<<dim3(DM/64, ROWS/64), 256>>>(x, W_proj, ph, DM, DIN, 1, pm);

    for (int l=0; l<L_LAYERS; l++){
        gemm_nn<<<dim3(HD/64, ROWS/64), 256>>>(ph, Wq + (long)l*DM*HD, pq, HD, DM, 0, nullptr);
        gemm_nn<<<dim3(HD/64, ROWS/64), 256>>>(ph, Wk + (long)l*DM*HD, pk, HD, DM, 0, nullptr);
        gemm_nn<<<dim3(HD/64, ROWS/64), 256>>>(ph, Wv + (long)l*DM*HD, pv, HD, DM, 0, nullptr);
        attn_kernel<<<dim3(H_HEADS, S_SETS), 256, ATTN_SMEM>>>(pq, pk, pv, po);
        gemm_nn<<<dim3(DM/64, ROWS/64), 256>>>(po, Wh + (long)l*HD*DM, pt, DM, HD, 0, nullptr);
        setnorm_kernel<<<S_SETS, 256, SN_SMEM>>>(ph, pt, pm, x_size, 0);
        gemm_nn<<<dim3(DM/64, ROWS/64), 256>>>(ph, Wfc + (long)l*DM*DM, pt, DM, DM, 0, nullptr);
        setnorm_kernel<<<S_SETS, 256, SN_SMEM>>>(ph, pt, pm, x_size, 1);
    }

    gemm_nn<<<dim3(HD/64, ROWS/64), 256>>>(ph, Wc, pz, HD, DM, 0, nullptr);
    gram_wmma_kernel<<<dim3(S_SETS*(S_SETS+1)/2, H_HEADS), 256, GRAM_SMEM>>>(pz, pB);
    final_kernel<<<(S_SETS*S_SETS + 255)/256, 256>>>(pB, x_size, w2, out);
}

// round 3
// speedup vs baseline: 2.4712x; 1.8011x over previous
#include <cuda_runtime.h>
#include <cuda_bf16.h>
#include <math.h>
#include <mma.h>

using namespace nvcuda;

#define S_SETS 48
#define M_ITEMS 128
#define DIN 128
#define DM 128
#define H_HEADS 4
#define DH 128
#define L_LAYERS 2
#define ROWS (S_SETS*M_ITEMS)   /* 6144 */
#define HD (H_HEADS*DH)         /* 512  */

#define PA 130   /* attn smem pitches */
#define PB 129
#define PV 132

#define PAs 36   /* gemm A-tile pitch (floats) */
#define PBs 68   /* gemm B-tile pitch (floats) */
#define PCs 68   /* gemm C-tile pitch (floats) */
#define PZ 136   /* gram bf16 pitch (elements, mult of 8) */

// ---------------- device scratch ----------------
__device__ float g_mask[ROWS];
__device__ float g_h[ROWS*DM];
__device__ float g_q[ROWS*HD];
__device__ float g_k[ROWS*HD];
__device__ float g_v[ROWS*HD];
__device__ float g_o[ROWS*HD];
__device__ float g_t[ROWS*DM];
__device__ float g_z[ROWS*HD];
__device__ float g_B[S_SETS*S_SETS*H_HEADS];

__device__ __forceinline__ float gelu_f(float x){
    return 0.5f*x*(1.0f + erff(x*0.70710678118654752440f));
}

__device__ __forceinline__ float block_reduce_sum(float v, float* red){
    int tid = threadIdx.x;
    #pragma unroll
    for (int o=16;o;o>>=1) v += __shfl_xor_sync(0xffffffffu, v, o);
    if ((tid&31)==0) red[tid>>5] = v;
    __syncthreads();
    if (tid < 32) {
        float r = (tid < 8) ? red[tid] : 0.0f;
        #pragma unroll
        for (int o=4;o;o>>=1) r += __shfl_xor_sync(0xffffffffu, r, o);
        if (tid==0) red[0] = r;
    }
    __syncthreads();
    float out = red[0];
    __syncthreads();
    return out;
}

// ---------------- item mask ----------------
__global__ void mask_kernel(const float* __restrict__ x, float* __restrict__ mask){
    int row = blockIdx.x*8 + (threadIdx.x>>5);
    int lane = threadIdx.x & 31;
    float4 v = reinterpret_cast<const float4*>(x + (long)row*DIN)[lane];
    bool nz = (v.x!=0.0f)||(v.y!=0.0f)||(v.z!=0.0f)||(v.w!=0.0f);
    unsigned b = __ballot_sync(0xffffffffu, nz);
    if (lane==0) mask[row] = b ? 1.0f : 0.0f;
}

// ---------------- WMMA tf32 GEMM: C[6144,N] = A[6144,K] @ B[K,N] ----------------
// Block tile 128x64, 8 warps (4x2), warp tile 32x32 (2x2 m16n16k8 frags), K-chunk 32.
// epi: 0 = none, 1 = gelu(c)*mask[row]
__global__ __launch_bounds__(256) void gemm_wmma(
    const float* __restrict__ A, const float* __restrict__ B, float* __restrict__ C,
    int N, int K, int epi, const float* __restrict__ mask)
{
    __shared__ float sm[128*PCs];     // 34816B; front reused: As[128*PAs] + Bs[32*PBs]
    float* As = sm;                   // 128 x 32, pitch PAs
    float* Bs = sm + 128*PAs;         // 32 x 64, pitch PBs
    int tid = threadIdx.x;
    int warp = tid >> 5;
    int wr = warp >> 1, wc = warp & 1;
    int row0 = blockIdx.y*128, col0 = blockIdx.x*64;

    wmma::fragment<wmma::accumulator, 16, 16, 8, float> acc[2][2];
    #pragma unroll
    for (int i=0;i<2;i++)
        #pragma unroll
        for (int j=0;j<2;j++) wmma::fill_fragment(acc[i][j], 0.0f);

    for (int k0=0; k0<K; k0+=32){
        // stage A: 128x32 -> 1024 float4 slots
        #pragma unroll
        for (int t=0;t<4;t++){
            int idx = tid + t*256;
            int m = idx>>3, kg = idx&7;
            float4 a = *(const float4*)(A + (long)(row0+m)*K + k0 + kg*4);
            float* p = As + m*PAs + kg*4;
            p[0]=wmma::__float_to_tf32(a.x); p[1]=wmma::__float_to_tf32(a.y);
            p[2]=wmma::__float_to_tf32(a.z); p[3]=wmma::__float_to_tf32(a.w);
        }
        // stage B: 32x64 -> 512 float4 slots
        #pragma unroll
        for (int t=0;t<2;t++){
            int idx = tid + t*256;
            int kk = idx>>4, ng = idx&15;
            float4 b = *(const float4*)(B + (long)(k0+kk)*N + col0 + ng*4);
            float* p = Bs + kk*PBs + ng*4;
            p[0]=wmma::__float_to_tf32(b.x); p[1]=wmma::__float_to_tf32(b.y);
            p[2]=wmma::__float_to_tf32(b.z); p[3]=wmma::__float_to_tf32(b.w);
        }
        __syncthreads();
        #pragma unroll
        for (int ks=0; ks<4; ks++){
            wmma::fragment<wmma::matrix_a, 16, 16, 8, wmma::precision::tf32, wmma::row_major> a0, a1;
            wmma::fragment<wmma::matrix_b, 16, 16, 8, wmma::precision::tf32, wmma::row_major> b0, b1;
            wmma::load_matrix_sync(a0, As + (wr*32    )*PAs + ks*8, PAs);
            wmma::load_matrix_sync(a1, As + (wr*32+16 )*PAs + ks*8, PAs);
            wmma::load_matrix_sync(b0, Bs + (ks*8)*PBs + wc*32,      PBs);
            wmma::load_matrix_sync(b1, Bs + (ks*8)*PBs + wc*32 + 16, PBs);
            wmma::mma_sync(acc[0][0], a0, b0, acc[0][0]);
            wmma::mma_sync(acc[0][1], a0, b1, acc[0][1]);
            wmma::mma_sync(acc[1][0], a1, b0, acc[1][0]);
            wmma::mma_sync(acc[1][1], a1, b1, acc[1][1]);
        }
        __syncthreads();
    }

    // epilogue through smem
    #pragma unroll
    for (int i=0;i<2;i++)
        #pragma unroll
        for (int j=0;j<2;j++)
            wmma::store_matrix_sync(sm + (wr*32+i*16)*PCs + wc*32 + j*16, acc[i][j], PCs, wmma::mem_row_major);
    __syncthreads();
    #pragma unroll
    for (int t=0;t<8;t++){
        int idx = tid + t*256;
        int m = idx>>4, ng = idx&15;
        int r = row0 + m;
        const float* p = sm + m*PCs + ng*4;
        float4 outv;
        if (epi==1){
            float mrow = mask[r];
            outv.x = gelu_f(p[0])*mrow; outv.y = gelu_f(p[1])*mrow;
            outv.z = gelu_f(p[2])*mrow; outv.w = gelu_f(p[3])*mrow;
        } else {
            outv.x = p[0]; outv.y = p[1]; outv.z = p[2]; outv.w = p[3];
        }
        *(float4*)(C + (long)r*N + col0 + ng*4) = outv;
    }
}

// ---------------- fused attention per (head, set) — fp32 SIMT ----------------
__global__ __launch_bounds__(256) void attn_kernel(
    const float* __restrict__ q, const float* __restrict__ k,
    const float* __restrict__ v, float* __restrict__ o)
{
    int h = blockIdx.x, s = blockIdx.y;
    extern __shared__ float sm[];
    float* qs = sm;
    float* ks = sm + 128*PA;
    float* vs = sm + 128*PA + 128*PB;
    int tid = threadIdx.x;
    long base = (long)(s*M_ITEMS)*HD + h*DH;

    for (int idx=tid; idx<128*32; idx+=256){
        int m = idx>>5, dg = idx&31;
        float4 a = *(const float4*)(q + base + (long)m*HD + dg*4);
        float4 b = *(const float4*)(k + base + (long)m*HD + dg*4);
        float4 c = *(const float4*)(v + base + (long)m*HD + dg*4);
        float* pq = qs + m*PA + dg*4; pq[0]=a.x; pq[1]=a.y; pq[2]=a.z; pq[3]=a.w;
        float* pk = ks + m*PB + dg*4; pk[0]=b.x; pk[1]=b.y; pk[2]=b.z; pk[3]=b.w;
        float* pv = vs + m*PV + dg*4; pv[0]=c.x; pv[1]=c.y; pv[2]=c.z; pv[3]=c.w;
    }
    __syncthreads();

    int tx = tid&15, ty = tid>>4;
    int m0 = ty*8, n0 = tx*8;
    float acc[8][8] = {};
    for (int d=0; d<128; d++){
        float af[8], bf[8];
        #pragma unroll
        for (int i=0;i<8;i++) af[i] = qs[(m0+i)*PA + d];
        #pragma unroll
        for (int j=0;j<8;j++) bf[j] = ks[(n0+j)*PB + d];
        #pragma unroll
        for (int i=0;i<8;i++)
            #pragma unroll
            for (int j=0;j<8;j++) acc[i][j] += af[i]*bf[j];
    }
    __syncthreads();
    const float scale = 0.08838834764831844f;
    #pragma unroll
    for (int i=0;i<8;i++)
        #pragma unroll
        for (int j=0;j<8;j++) qs[(m0+i)*PA + n0+j] = acc[i][j]*scale;
    __syncthreads();

    int warp = tid>>5, lane = tid&31;
    for (int m=warp; m<128; m+=8){
        float* row = qs + m*PA;
        float vals[4]; float mx = -INFINITY;
        #pragma unroll
        for (int r=0;r<4;r++){ vals[r] = row[lane+32*r]; mx = fmaxf(mx, vals[r]); }
        #pragma unroll
        for (int off=16;off;off>>=1) mx = fmaxf(mx, __shfl_xor_sync(0xffffffffu, mx, off));
        float sum = 0.0f;
        #pragma unroll
        for (int r=0;r<4;r++){
            float e = (vals[r]!=0.0f) ? expf(vals[r]-mx) : 0.0f;
            vals[r] = e; sum += e;
        }
        #pragma unroll
        for (int off=16;off;off>>=1) sum += __shfl_xor_sync(0xffffffffu, sum, off);
        float inv = 1.0f/(sum + 1e-10f);
        #pragma unroll
        for (int r=0;r<4;r++) row[lane+32*r] = vals[r]*inv;
    }
    __syncthreads();

    float acc2[8][8] = {};
    for (int n=0;n<128;n++){
        float af[8];
        #pragma unroll
        for (int i=0;i<8;i++) af[i] = qs[(m0+i)*PA + n];
        float4 b0 = *(const float4*)(vs + n*PV + n0);
        float4 b1 = *(const float4*)(vs + n*PV + n0 + 4);
        #pragma unroll
        for (int i=0;i<8;i++){
            acc2[i][0] += af[i]*b0.x; acc2[i][1] += af[i]*b0.y;
            acc2[i][2] += af[i]*b0.z; acc2[i][3] += af[i]*b0.w;
            acc2[i][4] += af[i]*b1.x; acc2[i][5] += af[i]*b1.y;
            acc2[i][6] += af[i]*b1.z; acc2[i][7] += af[i]*b1.w;
        }
    }
    #pragma unroll
    for (int i=0;i<8;i++)
        #pragma unroll
        for (int j=0;j<8;j++)
            o[base + (long)(m0+i)*HD + n0 + j] = acc2[i][j];
}

// ---------------- set_norm fused with residual add (+ optional gelu) ----------------
__global__ __launch_bounds__(256) void setnorm_kernel(
    float* __restrict__ hbuf, const float* __restrict__ abuf,
    const float* __restrict__ mitem, const int* __restrict__ x_size,
    int apply_gelu)
{
    int s = blockIdx.x;
    extern __shared__ float sm[];
    float* ts = sm;
    float* rs = sm + 128*130;
    __shared__ float red[32];
    int tid = threadIdx.x;
    long base = (long)s*M_ITEMS*DM;

    for (int idx=tid; idx<128*32; idx+=256){
        int m = idx>>5, dg = idx&31;
        float mrow = mitem[s*M_ITEMS+m];
        float4 hv = *(const float4*)(hbuf + base + (long)m*DM + dg*4);
        float4 av = *(const float4*)(abuf + base + (long)m*DM + dg*4);
        float a0 = apply_gelu ? gelu_f(av.x) : av.x;
        float a1 = apply_gelu ? gelu_f(av.y) : av.y;
        float a2 = apply_gelu ? gelu_f(av.z) : av.z;
        float a3 = apply_gelu ? gelu_f(av.w) : av.w;
        float* pt = ts + m*130 + dg*4;
        pt[0] = hv.x + a0*mrow; pt[1] = hv.y + a1*mrow;
        pt[2] = hv.z + a2*mrow; pt[3] = hv.w + a3*mrow;
    }
    __syncthreads();

    int warp = tid>>5, lane = tid&31;
    for (int m=warp; m<128; m+=8){
        float v = ts[m*130+lane] + ts[m*130+lane+32] + ts[m*130+lane+64] + ts[m*130+lane+96];
        #pragma unroll
        for (int off=16;off;off>>=1) v += __shfl_xor_sync(0xffffffffu, v, off);
        if (lane==0) rs[m] = v;
    }
    __syncthreads();

    float tv = (tid<128) ? rs[tid] : 0.0f;
    float total = block_reduce_sum(tv, red);
    int szi = x_size[s]; if (szi < 1) szi = 1;
    float denom = (float)szi * 128.0f;
    float mean = total / denom;

    float vv = 0.0f;
    for (int idx=tid; idx<128*32; idx+=256){
        int m = idx>>5, dg = idx&31;
        if (rs[m] != 0.0f){
            float* pt = ts + m*130 + dg*4;
            float d0 = pt[0]-mean, d1 = pt[1]-mean, d2 = pt[2]-mean, d3 = pt[3]-mean;
            vv += d0*d0 + d1*d1 + d2*d2 + d3*d3;
        }
    }
    float vart = block_reduce_sum(vv, red);
    float inv = 1.0f/(sqrtf(vart/denom) + 1e-8f);

    for (int idx=tid; idx<128*32; idx+=256){
        int m = idx>>5, dg = idx&31;
        float mr = (rs[m] != 0.0f) ? 1.0f : 0.0f;
        float* pt = ts + m*130 + dg*4;
        float4 outv;
        outv.x = (pt[0]-mean)*inv*mr;
        outv.y = (pt[1]-mean)*inv*mr;
        outv.z = (pt[2]-mean)*inv*mr;
        outv.w = (pt[3]-mean)*inv*mr;
        *(float4*)(hbuf + base + (long)m*DM + dg*4) = outv;
    }
}

// ---------------- cross-set Gram via WMMA bf16 (m16n16k16) ----------------
// One block per (pair, head). Warp tile 32x64: per k-step 6 loads / 8 MMAs.
__global__ __launch_bounds__(256) void gram_bf16_kernel(
    const float* __restrict__ z, float* __restrict__ Bout)
{
    int h = blockIdx.y;
    int p = blockIdx.x;
    int j = 0, rem = p;
    while (rem >= S_SETS - j){ rem -= S_SETS - j; j++; }
    int i = j + rem;

    extern __shared__ __nv_bfloat16 smb[];
    __nv_bfloat16* zj = smb;             // [128][PZ]  A row-major m x k
    __nv_bfloat16* zi = smb + 128*PZ;    // [128][PZ]  B col-major k x n (row n holds k)
    __shared__ float red[32];
    int tid = threadIdx.x;
    int warp = tid >> 5;
    int wr = warp >> 1, wc = warp & 1;
    long basej = (long)(j*M_ITEMS)*HD + h*DH;
    long basei = (long)(i*M_ITEMS)*HD + h*DH;

    for (int idx=tid; idx<128*32; idx+=256){
        int m = idx>>5, dg = idx&31;
        float4 a = *(const float4*)(z + basej + (long)m*HD + dg*4);
        float4 b = *(const float4*)(z + basei + (long)m*HD + dg*4);
        __nv_bfloat162* pa = (__nv_bfloat162*)(zj + m*PZ + dg*4);
        pa[0] = __floats2bfloat162_rn(a.x, a.y);
        pa[1] = __floats2bfloat162_rn(a.z, a.w);
        __nv_bfloat162* pb = (__nv_bfloat162*)(zi + m*PZ + dg*4);
        pb[0] = __floats2bfloat162_rn(b.x, b.y);
        pb[1] = __floats2bfloat162_rn(b.z, b.w);
    }
    __syncthreads();

    wmma::fragment<wmma::accumulator, 16, 16, 16, float> acc[2][4];
    #pragma unroll
    for (int a=0;a<2;a++)
        #pragma unroll
        for (int t=0;t<4;t++) wmma::fill_fragment(acc[a][t], 0.0f);

    #pragma unroll
    for (int ks=0; ks<8; ks++){
        wmma::fragment<wmma::matrix_a, 16, 16, 16, __nv_bfloat16, wmma::row_major> a0, a1;
        wmma::load_matrix_sync(a0, zj + (wr*32    )*PZ + ks*16, PZ);
        wmma::load_matrix_sync(a1, zj + (wr*32+16 )*PZ + ks*16, PZ);
        #pragma unroll
        for (int t=0;t<4;t++){
            wmma::fragment<wmma::matrix_b, 16, 16, 16, __nv_bfloat16, wmma::col_major> bfrag;
            wmma::load_matrix_sync(bfrag, zi + (wc*64 + t*16)*PZ + ks*16, PZ);
            wmma::mma_sync(acc[0][t], a0, bfrag, acc[0][t]);
            wmma::mma_sync(acc[1][t], a1, bfrag, acc[1][t]);
        }
    }

    const float scale = 0.08838834764831844f;
    float lsum = 0.0f;
    #pragma unroll
    for (int a=0;a<2;a++)
        #pragma unroll
        for (int t=0;t<4;t++)
            #pragma unroll
            for (int e=0;e<acc[a][t].num_elements;e++){
                float vv = acc[a][t].x[e]*scale;
                lsum += (vv >= 0.0f) ? vv : 0.3f*vv;
            }
    float total = block_reduce_sum(lsum, red);
    if (tid==0){
        Bout[(j*S_SETS+i)*H_HEADS + h] = total;
        Bout[(i*S_SETS+j)*H_HEADS + h] = total;
    }
}

// ---------------- finalize ----------------
__global__ void final_kernel(const float* __restrict__ Bm, const int* __restrict__ x_size,
                             const float* __restrict__ w2, float* __restrict__ out)
{
    int idx = blockIdx.x*256 + threadIdx.x;
    if (idx >= S_SETS*S_SETS) return;
    int j = idx / S_SETS, i = idx % S_SETS;
    int szi = x_size[i]; if (szi < 1) szi = 1;
    float acc = 0.0f;
    #pragma unroll
    for (int h=0; h<H_HEADS; h++) acc += Bm[(j*S_SETS+i)*H_HEADS + h] * w2[h];
    out[idx] = acc / (float)szi / (float)M_ITEMS;
}

// ---------------- launch ----------------
extern "C" void kernel_launch(void* const* d_in, const int* in_sizes, int n_in,
                              void* d_out, int out_size)
{
    const float* x      = (const float*)d_in[0];
    const int*   x_size = (const int*)  d_in[1];
    const float* W_proj = (const float*)d_in[2];
    const float* Wq     = (const float*)d_in[3];
    const float* Wk     = (const float*)d_in[4];
    const float* Wv     = (const float*)d_in[5];
    const float* Wh     = (const float*)d_in[6];
    const float* Wfc    = (const float*)d_in[7];
    const float* Wc     = (const float*)d_in[8];
    const float* w2     = (const float*)d_in[9];
    float* out = (float*)d_out;

    float *pm, *ph, *pq, *pk, *pv, *po, *pt, *pz, *pB;
    cudaGetSymbolAddress((void**)&pm, g_mask);
    cudaGetSymbolAddress((void**)&ph, g_h);
    cudaGetSymbolAddress((void**)&pq, g_q);
    cudaGetSymbolAddress((void**)&pk, g_k);
    cudaGetSymbolAddress((void**)&pv, g_v);
    cudaGetSymbolAddress((void**)&po, g_o);
    cudaGetSymbolAddress((void**)&pt, g_t);
    cudaGetSymbolAddress((void**)&pz, g_z);
    cudaGetSymbolAddress((void**)&pB, g_B);

    const int ATTN_SMEM = 128*(PA+PB+PV)*4;     // 200192 B
    const int GRAM_SMEM = 2*128*PZ*2;           //  69632 B
    const int SN_SMEM   = 128*130*4 + 128*4;    //  67072 B
    cudaFuncSetAttribute(attn_kernel,      cudaFuncAttributeMaxDynamicSharedMemorySize, ATTN_SMEM);
    cudaFuncSetAttribute(gram_bf16_kernel, cudaFuncAttributeMaxDynamicSharedMemorySize, GRAM_SMEM);
    cudaFuncSetAttribute(setnorm_kernel,   cudaFuncAttributeMaxDynamicSharedMemorySize, SN_SMEM);

    mask_kernel<<<ROWS/8, 256>>>(x, pm);
    gemm_wmma<<<dim3(DM/64, ROWS/128), 256>>>(x, W_proj, ph, DM, DIN, 1, pm);

    for (int l=0; l<L_LAYERS; l++){
        gemm_wmma<<<dim3(HD/64, ROWS/128), 256>>>(ph, Wq + (long)l*DM*HD, pq, HD, DM, 0, nullptr);
        gemm_wmma<<<dim3(HD/64, ROWS/128), 256>>>(ph, Wk + (long)l*DM*HD, pk, HD, DM, 0, nullptr);
        gemm_wmma<<<dim3(HD/64, ROWS/128), 256>>>(ph, Wv + (long)l*DM*HD, pv, HD, DM, 0, nullptr);
        attn_kernel<<<dim3(H_HEADS, S_SETS), 256, ATTN_SMEM>>>(pq, pk, pv, po);
        gemm_wmma<<<dim3(DM/64, ROWS/128), 256>>>(po, Wh + (long)l*HD*DM, pt, DM, HD, 0, nullptr);
        setnorm_kernel<<<S_SETS, 256, SN_SMEM>>>(ph, pt, pm, x_size, 0);
        gemm_wmma<<<dim3(DM/64, ROWS/128), 256>>>(ph, Wfc + (long)l*DM*DM, pt, DM, DM, 0, nullptr);
        setnorm_kernel<<<S_SETS, 256, SN_SMEM>>>(ph, pt, pm, x_size, 1);
    }

    gemm_wmma<<<dim3(HD/64, ROWS/128), 256>>>(ph, Wc, pz, HD, DM, 0, nullptr);
    gram_bf16_kernel<<<dim3(S_SETS*(S_SETS+1)/2, H_HEADS), 256, GRAM_SMEM>>>(pz, pB);
    final_kernel<<<(S_SETS*S_SETS + 255)/256, 256>>>(pB, x_size, w2, out);
}

// round 7
// speedup vs baseline: 2.9329x; 1.1868x over previous
#include <cuda_runtime.h>
#include <cuda_bf16.h>
#include <math.h>
#include <mma.h>

using namespace nvcuda;

#define S_SETS 48
#define M_ITEMS 128
#define DIN 128
#define DM 128
#define H_HEADS 4
#define DH 128
#define L_LAYERS 2
#define ROWS (S_SETS*M_ITEMS)   /* 6144 */
#define HD (H_HEADS*DH)         /* 512  */
#define QKVW 1536               /* packed qkv width */

#define PAs 36   /* gemm A-tile pitch (floats) */
#define PBs 68   /* gemm B-tile pitch (floats) */
#define PCs 68   /* gemm C-tile pitch (floats) */
#define PT 132   /* attn smem pitch (floats) */
#define PZ 136   /* gram bf16 pitch */

// ---------------- device scratch ----------------
__device__ float g_mask[ROWS];
__device__ float g_h[ROWS*DM];
__device__ float g_qkv[ROWS*QKVW];
__device__ float g_wqkv[DM*QKVW];
__device__ float g_o[ROWS*HD];
__device__ float g_t[ROWS*DM];
__device__ float g_z[ROWS*HD];
__device__ float g_B[S_SETS*S_SETS*H_HEADS];

__device__ __forceinline__ float gelu_f(float x){
    return 0.5f*x*(1.0f + erff(x*0.70710678118654752440f));
}

__device__ __forceinline__ float block_reduce_sum(float v, float* red){
    int tid = threadIdx.x;
    #pragma unroll
    for (int o=16;o;o>>=1) v += __shfl_xor_sync(0xffffffffu, v, o);
    if ((tid&31)==0) red[tid>>5] = v;
    __syncthreads();
    if (tid < 32) {
        float r = (tid < 8) ? red[tid] : 0.0f;
        #pragma unroll
        for (int o=4;o;o>>=1) r += __shfl_xor_sync(0xffffffffu, r, o);
        if (tid==0) red[0] = r;
    }
    __syncthreads();
    float out = red[0];
    __syncthreads();
    return out;
}

// ---------------- item mask ----------------
__global__ void mask_kernel(const float* __restrict__ x, float* __restrict__ mask){
    int row = blockIdx.x*8 + (threadIdx.x>>5);
    int lane = threadIdx.x & 31;
    float4 v = reinterpret_cast<const float4*>(x + (long)row*DIN)[lane];
    bool nz = (v.x!=0.0f)||(v.y!=0.0f)||(v.z!=0.0f)||(v.w!=0.0f);
    unsigned b = __ballot_sync(0xffffffffu, nz);
    if (lane==0) mask[row] = b ? 1.0f : 0.0f;
}

// ---------------- pack Wq|Wk|Wv into [128][1536] ----------------
__global__ void pack_qkv_kernel(const float* __restrict__ Wq, const float* __restrict__ Wk,
                                const float* __restrict__ Wv, float* __restrict__ W){
    int t = blockIdx.x*256 + threadIdx.x;
    int r = t >> 7, c4 = t & 127;
    const float4* q4 = (const float4*)Wq;
    const float4* k4 = (const float4*)Wk;
    const float4* v4 = (const float4*)Wv;
    float4* w4 = (float4*)W;
    w4[r*384 + c4      ] = q4[r*128 + c4];
    w4[r*384 + 128 + c4] = k4[r*128 + c4];
    w4[r*384 + 256 + c4] = v4[r*128 + c4];
}

// ---------------- register-pipelined WMMA-tf32 GEMM (RN conversion) ----------------
// Block tile 128x64, 8 warps (4x2), warp tile 32x32, K-chunk 32.
__global__ __launch_bounds__(256) void gemm_tf32(
    const float* __restrict__ A, const float* __restrict__ B, float* __restrict__ C,
    int N, int K, int epi, const float* __restrict__ mask)
{
    __shared__ float sm[128*PCs];     // epilogue needs 128*PCs; mainloop uses front part
    float* As = sm;                   // 128 x PAs
    float* Bs = sm + 128*PAs;         // 32 x PBs
    int tid = threadIdx.x;
    int warp = tid >> 5;
    int wr = warp >> 1, wc = warp & 1;
    int row0 = blockIdx.y*128, col0 = blockIdx.x*64;

    wmma::fragment<wmma::accumulator, 16, 16, 8, float> acc[2][2];
    #pragma unroll
    for (int i=0;i<2;i++)
        #pragma unroll
        for (int j=0;j<2;j++) wmma::fill_fragment(acc[i][j], 0.0f);

    float4 ra[4], rb[2];
    auto gload = [&](int k0){
        #pragma unroll
        for (int t=0;t<4;t++){
            int idx = tid + t*256;
            int m = idx>>3, kg = idx&7;
            ra[t] = *(const float4*)(A + (long)(row0+m)*K + k0 + kg*4);
        }
        #pragma unroll
        for (int t=0;t<2;t++){
            int idx = tid + t*256;
            int kk = idx>>4, ng = idx&15;
            rb[t] = *(const float4*)(B + (long)(k0+kk)*N + col0 + ng*4);
        }
    };
    auto swrite = [&](){
        #pragma unroll
        for (int t=0;t<4;t++){
            int idx = tid + t*256;
            int m = idx>>3, kg = idx&7;
            float* p = As + m*PAs + kg*4;
            p[0]=wmma::__float_to_tf32(ra[t].x); p[1]=wmma::__float_to_tf32(ra[t].y);
            p[2]=wmma::__float_to_tf32(ra[t].z); p[3]=wmma::__float_to_tf32(ra[t].w);
        }
        #pragma unroll
        for (int t=0;t<2;t++){
            int idx = tid + t*256;
            int kk = idx>>4, ng = idx&15;
            float* p = Bs + kk*PBs + ng*4;
            p[0]=wmma::__float_to_tf32(rb[t].x); p[1]=wmma::__float_to_tf32(rb[t].y);
            p[2]=wmma::__float_to_tf32(rb[t].z); p[3]=wmma::__float_to_tf32(rb[t].w);
        }
    };

    int nch = K >> 5;
    gload(0);
    for (int c=0; c<nch; c++){
        swrite();
        __syncthreads();
        if (c+1 < nch) gload((c+1)*32);   // overlap gmem latency with MMAs below
        #pragma unroll
        for (int ks=0; ks<4; ks++){
            wmma::fragment<wmma::matrix_a, 16, 16, 8, wmma::precision::tf32, wmma::row_major> a0, a1;
            wmma::fragment<wmma::matrix_b, 16, 16, 8, wmma::precision::tf32, wmma::row_major> b0, b1;
            wmma::load_matrix_sync(a0, As + (wr*32    )*PAs + ks*8, PAs);
            wmma::load_matrix_sync(a1, As + (wr*32+16 )*PAs + ks*8, PAs);
            wmma::load_matrix_sync(b0, Bs + (ks*8)*PBs + wc*32,      PBs);
            wmma::load_matrix_sync(b1, Bs + (ks*8)*PBs + wc*32 + 16, PBs);
            wmma::mma_sync(acc[0][0], a0, b0, acc[0][0]);
            wmma::mma_sync(acc[0][1], a0, b1, acc[0][1]);
            wmma::mma_sync(acc[1][0], a1, b0, acc[1][0]);
            wmma::mma_sync(acc[1][1], a1, b1, acc[1][1]);
        }
        __syncthreads();
    }

    #pragma unroll
    for (int i=0;i<2;i++)
        #pragma unroll
        for (int j=0;j<2;j++)
            wmma::store_matrix_sync(sm + (wr*32+i*16)*PCs + wc*32 + j*16, acc[i][j], PCs, wmma::mem_row_major);
    __syncthreads();
    #pragma unroll
    for (int t=0;t<8;t++){
        int idx = tid + t*256;
        int m = idx>>4, ng = idx&15;
        int r = row0 + m;
        const float* p = sm + m*PCs + ng*4;
        float4 outv;
        if (epi==1){
            float mrow = mask[r];
            outv.x = gelu_f(p[0])*mrow; outv.y = gelu_f(p[1])*mrow;
            outv.z = gelu_f(p[2])*mrow; outv.w = gelu_f(p[3])*mrow;
        } else {
            outv.x = p[0]; outv.y = p[1]; outv.z = p[2]; outv.w = p[3];
        }
        *(float4*)(C + (long)r*N + col0 + ng*4) = outv;
    }
}

// ---------------- attention per (head, set): WMMA-tf32 matmuls, RN everywhere ----------------
__global__ __launch_bounds__(256) void attn_wmma(
    const float* __restrict__ qkv, float* __restrict__ o)
{
    int h = blockIdx.x, s = blockIdx.y;
    extern __shared__ float sm[];
    float* qs = sm;                  // Q (tf32), later scores fp32 / probs tf32
    float* ks = sm + 128*PT;
    float* vs = sm + 2*128*PT;
    int tid = threadIdx.x;
    int warp = tid >> 5, lane = tid & 31;
    int wr = warp >> 1, wc = warp & 1;
    long base = (long)(s*M_ITEMS)*QKVW + h*DH;

    for (int idx=tid; idx<128*32; idx+=256){
        int m = idx>>5, dg = idx&31;
        const float* rowp = qkv + base + (long)m*QKVW + dg*4;
        float4 a = *(const float4*)(rowp);
        float4 b = *(const float4*)(rowp + 512);
        float4 c = *(const float4*)(rowp + 1024);
        float* pq = qs + m*PT + dg*4;
        pq[0]=wmma::__float_to_tf32(a.x); pq[1]=wmma::__float_to_tf32(a.y);
        pq[2]=wmma::__float_to_tf32(a.z); pq[3]=wmma::__float_to_tf32(a.w);
        float* pk = ks + m*PT + dg*4;
        pk[0]=wmma::__float_to_tf32(b.x); pk[1]=wmma::__float_to_tf32(b.y);
        pk[2]=wmma::__float_to_tf32(b.z); pk[3]=wmma::__float_to_tf32(b.w);
        float* pv = vs + m*PT + dg*4;
        pv[0]=wmma::__float_to_tf32(c.x); pv[1]=wmma::__float_to_tf32(c.y);
        pv[2]=wmma::__float_to_tf32(c.z); pv[3]=wmma::__float_to_tf32(c.w);
    }
    __syncthreads();

    const float scale = 0.08838834764831844f;  // 1/sqrt(128)

    // S = Q @ K^T * scale ; warp tile 32x64; scores stored fp32
    {
        wmma::fragment<wmma::accumulator, 16, 16, 8, float> acc[2][4];
        #pragma unroll
        for (int i=0;i<2;i++)
            #pragma unroll
            for (int t=0;t<4;t++) wmma::fill_fragment(acc[i][t], 0.0f);
        #pragma unroll
        for (int k8=0; k8<16; k8++){
            wmma::fragment<wmma::matrix_a, 16, 16, 8, wmma::precision::tf32, wmma::row_major> a0, a1;
            wmma::load_matrix_sync(a0, qs + (wr*32    )*PT + k8*8, PT);
            wmma::load_matrix_sync(a1, qs + (wr*32+16 )*PT + k8*8, PT);
            #pragma unroll
            for (int t=0;t<4;t++){
                wmma::fragment<wmma::matrix_b, 16, 16, 8, wmma::precision::tf32, wmma::col_major> bf;
                wmma::load_matrix_sync(bf, ks + (wc*64 + t*16)*PT + k8*8, PT);
                wmma::mma_sync(acc[0][t], a0, bf, acc[0][t]);
                wmma::mma_sync(acc[1][t], a1, bf, acc[1][t]);
            }
        }
        __syncthreads();
        #pragma unroll
        for (int i=0;i<2;i++)
            #pragma unroll
            for (int t=0;t<4;t++){
                #pragma unroll
                for (int e=0;e<acc[i][t].num_elements;e++) acc[i][t].x[e] *= scale;
                wmma::store_matrix_sync(qs + (wr*32+i*16)*PT + wc*64 + t*16, acc[i][t], PT, wmma::mem_row_major);
            }
        __syncthreads();
    }

    // masked softmax per row (fp32); write P back as tf32(RN)
    for (int m=warp; m<128; m+=8){
        float* row = qs + m*PT;
        float vals[4]; float mx = -INFINITY;
        #pragma unroll
        for (int r=0;r<4;r++){ vals[r] = row[lane+32*r]; mx = fmaxf(mx, vals[r]); }
        #pragma unroll
        for (int off=16;off;off>>=1) mx = fmaxf(mx, __shfl_xor_sync(0xffffffffu, mx, off));
        float sum = 0.0f;
        #pragma unroll
        for (int r=0;r<4;r++){
            float e = (vals[r]!=0.0f) ? expf(vals[r]-mx) : 0.0f;
            vals[r] = e; sum += e;
        }
        #pragma unroll
        for (int off=16;off;off>>=1) sum += __shfl_xor_sync(0xffffffffu, sum, off);
        float inv = 1.0f/(sum + 1e-10f);
        #pragma unroll
        for (int r=0;r<4;r++) row[lane+32*r] = wmma::__float_to_tf32(vals[r]*inv);
    }
    __syncthreads();

    // O = P @ V ; warp tile 32x64, store to global
    {
        long obase = (long)(s*M_ITEMS)*HD + h*DH;
        wmma::fragment<wmma::accumulator, 16, 16, 8, float> acc[2][4];
        #pragma unroll
        for (int i=0;i<2;i++)
            #pragma unroll
            for (int t=0;t<4;t++) wmma::fill_fragment(acc[i][t], 0.0f);
        #pragma unroll
        for (int k8=0; k8<16; k8++){
            wmma::fragment<wmma::matrix_a, 16, 16, 8, wmma::precision::tf32, wmma::row_major> a0, a1;
            wmma::load_matrix_sync(a0, qs + (wr*32    )*PT + k8*8, PT);
            wmma::load_matrix_sync(a1, qs + (wr*32+16 )*PT + k8*8, PT);
            #pragma unroll
            for (int t=0;t<4;t++){
                wmma::fragment<wmma::matrix_b, 16, 16, 8, wmma::precision::tf32, wmma::row_major> bf;
                wmma::load_matrix_sync(bf, vs + (k8*8)*PT + wc*64 + t*16, PT);
                wmma::mma_sync(acc[0][t], a0, bf, acc[0][t]);
                wmma::mma_sync(acc[1][t], a1, bf, acc[1][t]);
            }
        }
        #pragma unroll
        for (int i=0;i<2;i++)
            #pragma unroll
            for (int t=0;t<4;t++)
                wmma::store_matrix_sync(o + obase + (long)(wr*32+i*16)*HD + wc*64 + t*16, acc[i][t], HD, wmma::mem_row_major);
    }
}

// ---------------- set_norm fused with residual add (+ optional gelu) ----------------
__global__ __launch_bounds__(256) void setnorm_kernel(
    float* __restrict__ hbuf, const float* __restrict__ abuf,
    const float* __restrict__ mitem, const int* __restrict__ x_size,
    int apply_gelu)
{
    int s = blockIdx.x;
    extern __shared__ float sm[];
    float* ts = sm;
    float* rs = sm + 128*130;
    __shared__ float red[32];
    int tid = threadIdx.x;
    long base = (long)s*M_ITEMS*DM;

    for (int idx=tid; idx<128*32; idx+=256){
        int m = idx>>5, dg = idx&31;
        float mrow = mitem[s*M_ITEMS+m];
        float4 hv = *(const float4*)(hbuf + base + (long)m*DM + dg*4);
        float4 av = *(const float4*)(abuf + base + (long)m*DM + dg*4);
        float a0 = apply_gelu ? gelu_f(av.x) : av.x;
        float a1 = apply_gelu ? gelu_f(av.y) : av.y;
        float a2 = apply_gelu ? gelu_f(av.z) : av.z;
        float a3 = apply_gelu ? gelu_f(av.w) : av.w;
        float* pt = ts + m*130 + dg*4;
        pt[0] = hv.x + a0*mrow; pt[1] = hv.y + a1*mrow;
        pt[2] = hv.z + a2*mrow; pt[3] = hv.w + a3*mrow;
    }
    __syncthreads();

    int warp = tid>>5, lane = tid&31;
    for (int m=warp; m<128; m+=8){
        float v = ts[m*130+lane] + ts[m*130+lane+32] + ts[m*130+lane+64] + ts[m*130+lane+96];
        #pragma unroll
        for (int off=16;off;off>>=1) v += __shfl_xor_sync(0xffffffffu, v, off);
        if (lane==0) rs[m] = v;
    }
    __syncthreads();

    float tv = (tid<128) ? rs[tid] : 0.0f;
    float total = block_reduce_sum(tv, red);
    int szi = x_size[s]; if (szi < 1) szi = 1;
    float denom = (float)szi * 128.0f;
    float mean = total / denom;

    float vv = 0.0f;
    for (int idx=tid; idx<128*32; idx+=256){
        int m = idx>>5, dg = idx&31;
        if (rs[m] != 0.0f){
            float* pt = ts + m*130 + dg*4;
            float d0 = pt[0]-mean, d1 = pt[1]-mean, d2 = pt[2]-mean, d3 = pt[3]-mean;
            vv += d0*d0 + d1*d1 + d2*d2 + d3*d3;
        }
    }
    float vart = block_reduce_sum(vv, red);
    float inv = 1.0f/(sqrtf(vart/denom) + 1e-8f);

    for (int idx=tid; idx<128*32; idx+=256){
        int m = idx>>5, dg = idx&31;
        float mr = (rs[m] != 0.0f) ? 1.0f : 0.0f;
        float* pt = ts + m*130 + dg*4;
        float4 outv;
        outv.x = (pt[0]-mean)*inv*mr;
        outv.y = (pt[1]-mean)*inv*mr;
        outv.z = (pt[2]-mean)*inv*mr;
        outv.w = (pt[3]-mean)*inv*mr;
        *(float4*)(hbuf + base + (long)m*DM + dg*4) = outv;
    }
}

// ---------------- cross-set Gram via WMMA bf16 ----------------
__global__ __launch_bounds__(256) void gram_bf16_kernel(
    const float* __restrict__ z, float* __restrict__ Bout)
{
    int h = blockIdx.y;
    int p = blockIdx.x;
    int j = 0, rem = p;
    while (rem >= S_SETS - j){ rem -= S_SETS - j; j++; }
    int i = j + rem;

    extern __shared__ __nv_bfloat16 smb[];
    __nv_bfloat16* zj = smb;
    __nv_bfloat16* zi = smb + 128*PZ;
    __shared__ float red[32];
    int tid = threadIdx.x;
    int warp = tid >> 5;
    int wr = warp >> 1, wc = warp & 1;
    long basej = (long)(j*M_ITEMS)*HD + h*DH;
    long basei = (long)(i*M_ITEMS)*HD + h*DH;

    for (int idx=tid; idx<128*32; idx+=256){
        int m = idx>>5, dg = idx&31;
        float4 a = *(const float4*)(z + basej + (long)m*HD + dg*4);
        float4 b = *(const float4*)(z + basei + (long)m*HD + dg*4);
        __nv_bfloat162* pa = (__nv_bfloat162*)(zj + m*PZ + dg*4);
        pa[0] = __floats2bfloat162_rn(a.x, a.y);
        pa[1] = __floats2bfloat162_rn(a.z, a.w);
        __nv_bfloat162* pb = (__nv_bfloat162*)(zi + m*PZ + dg*4);
        pb[0] = __floats2bfloat162_rn(b.x, b.y);
        pb[1] = __floats2bfloat162_rn(b.z, b.w);
    }
    __syncthreads();

    wmma::fragment<wmma::accumulator, 16, 16, 16, float> acc[2][4];
    #pragma unroll
    for (int a=0;a<2;a++)
        #pragma unroll
        for (int t=0;t<4;t++) wmma::fill_fragment(acc[a][t], 0.0f);

    #pragma unroll
    for (int ks=0; ks<8; ks++){
        wmma::fragment<wmma::matrix_a, 16, 16, 16, __nv_bfloat16, wmma::row_major> a0, a1;
        wmma::load_matrix_sync(a0, zj + (wr*32    )*PZ + ks*16, PZ);
        wmma::load_matrix_sync(a1, zj + (wr*32+16 )*PZ + ks*16, PZ);
        #pragma unroll
        for (int t=0;t<4;t++){
            wmma::fragment<wmma::matrix_b, 16, 16, 16, __nv_bfloat16, wmma::col_major> bfrag;
            wmma::load_matrix_sync(bfrag, zi + (wc*64 + t*16)*PZ + ks*16, PZ);
            wmma::mma_sync(acc[0][t], a0, bfrag, acc[0][t]);
            wmma::mma_sync(acc[1][t], a1, bfrag, acc[1][t]);
        }
    }

    const float scale = 0.08838834764831844f;
    float lsum = 0.0f;
    #pragma unroll
    for (int a=0;a<2;a++)
        #pragma unroll
        for (int t=0;t<4;t++)
            #pragma unroll
            for (int e=0;e<acc[a][t].num_elements;e++){
                float vv = acc[a][t].x[e]*scale;
                lsum += (vv >= 0.0f) ? vv : 0.3f*vv;
            }
    float total = block_reduce_sum(lsum, red);
    if (tid==0){
        Bout[(j*S_SETS+i)*H_HEADS + h] = total;
        Bout[(i*S_SETS+j)*H_HEADS + h] = total;
    }
}

// ---------------- finalize ----------------
__global__ void final_kernel(const float* __restrict__ Bm, const int* __restrict__ x_size,
                             const float* __restrict__ w2, float* __restrict__ out)
{
    int idx = blockIdx.x*256 + threadIdx.x;
    if (idx >= S_SETS*S_SETS) return;
    int j = idx / S_SETS, i = idx % S_SETS;
    int szi = x_size[i]; if (szi < 1) szi = 1;
    float acc = 0.0f;
    #pragma unroll
    for (int h=0; h<H_HEADS; h++) acc += Bm[(j*S_SETS+i)*H_HEADS + h] * w2[h];
    out[idx] = acc / (float)szi / (float)M_ITEMS;
}

// ---------------- launch ----------------
extern "C" void kernel_launch(void* const* d_in, const int* in_sizes, int n_in,
                              void* d_out, int out_size)
{
    const float* x      = (const float*)d_in[0];
    const int*   x_size = (const int*)  d_in[1];
    const float* W_proj = (const float*)d_in[2];
    const float* Wq     = (const float*)d_in[3];
    const float* Wk     = (const float*)d_in[4];
    const float* Wv     = (const float*)d_in[5];
    const float* Wh     = (const float*)d_in[6];
    const float* Wfc    = (const float*)d_in[7];
    const float* Wc     = (const float*)d_in[8];
    const float* w2     = (const float*)d_in[9];
    float* out = (float*)d_out;

    float *pm, *ph, *pqkv, *pwqkv, *po, *pt, *pz, *pB;
    cudaGetSymbolAddress((void**)&pm, g_mask);
    cudaGetSymbolAddress((void**)&ph, g_h);
    cudaGetSymbolAddress((void**)&pqkv, g_qkv);
    cudaGetSymbolAddress((void**)&pwqkv, g_wqkv);
    cudaGetSymbolAddress((void**)&po, g_o);
    cudaGetSymbolAddress((void**)&pt, g_t);
    cudaGetSymbolAddress((void**)&pz, g_z);
    cudaGetSymbolAddress((void**)&pB, g_B);

    const int ATTN_SMEM = 3*128*PT*4;                 // 202752 B
    const int GRAM_SMEM = 2*128*PZ*2;                 //  69632 B
    const int SN_SMEM   = 128*130*4 + 128*4;          //  67072 B
    cudaFuncSetAttribute(attn_wmma,        cudaFuncAttributeMaxDynamicSharedMemorySize, ATTN_SMEM);
    cudaFuncSetAttribute(gram_bf16_kernel, cudaFuncAttributeMaxDynamicSharedMemorySize, GRAM_SMEM);
    cudaFuncSetAttribute(setnorm_kernel,   cudaFuncAttributeMaxDynamicSharedMemorySize, SN_SMEM);

    mask_kernel<<<ROWS/8, 256>>>(x, pm);
    gemm_tf32<<<dim3(DM/64, ROWS/128), 256>>>(x, W_proj, ph, DM, DIN, 1, pm);

    for (int l=0; l<L_LAYERS; l++){
        pack_qkv_kernel<<<64, 256>>>(Wq + (long)l*DM*HD, Wk + (long)l*DM*HD, Wv + (long)l*DM*HD, pwqkv);
        gemm_tf32<<<dim3(QKVW/64, ROWS/128), 256>>>(ph, pwqkv, pqkv, QKVW, DM, 0, nullptr);
        attn_wmma<<<dim3(H_HEADS, S_SETS), 256, ATTN_SMEM>>>(pqkv, po);
        gemm_tf32<<<dim3(DM/64, ROWS/128), 256>>>(po, Wh + (long)l*HD*DM, pt, DM, HD, 0, nullptr);
        setnorm_kernel<<<S_SETS, 256, SN_SMEM>>>(ph, pt, pm, x_size, 0);
        gemm_tf32<<<dim3(DM/64, ROWS/128), 256>>>(ph, Wfc + (long)l*DM*DM, pt, DM, DM, 0, nullptr);
        setnorm_kernel<<<S_SETS, 256, SN_SMEM>>>(ph, pt, pm, x_size, 1);
    }

    gemm_tf32<<<dim3(HD/64, ROWS/128), 256>>>(ph, Wc, pz, HD, DM, 0, nullptr);
    gram_bf16_kernel<<<dim3(S_SETS*(S_SETS+1)/2, H_HEADS), 256, GRAM_SMEM>>>(pz, pB);
    final_kernel<<<(S_SETS*S_SETS + 255)/256, 256>>>(pB, x_size, w2, out);
}

// round 8
// speedup vs baseline: 3.2756x; 1.1169x over previous
#include <cuda_runtime.h>
#include <cuda_bf16.h>
#include <math.h>
#include <mma.h>

using namespace nvcuda;

#define S_SETS 48
#define M_ITEMS 128
#define DIN 128
#define DM 128
#define H_HEADS 4
#define DH 128
#define L_LAYERS 2
#define ROWS (S_SETS*M_ITEMS)   /* 6144 */
#define HD (H_HEADS*DH)         /* 512  */
#define QKVW 1536               /* packed qkv width */

#define PAs 36   /* gemm A-tile pitch (floats) */
#define PBs 68   /* gemm B-tile pitch (floats) */
#define PCs 68   /* gemm C-tile pitch (floats) */
#define PT 132   /* attn smem pitch (floats) */
#define PZ 136   /* gram bf16 pitch */

// ---------------- device scratch ----------------
__device__ float g_mask[ROWS];
__device__ float g_x[ROWS*DIN];
__device__ float g_h[ROWS*DM];
__device__ float g_qkv[ROWS*QKVW];
__device__ float g_wproj[DIN*DM];
__device__ float g_wqkv[L_LAYERS*DM*QKVW];
__device__ float g_wh[L_LAYERS*HD*DM];
__device__ float g_wfc[L_LAYERS*DM*DM];
__device__ float g_wc[DM*HD];
__device__ float g_o[ROWS*HD];
__device__ float g_t[ROWS*DM];
__device__ float g_z[ROWS*HD];
__device__ float g_B[S_SETS*S_SETS*H_HEADS];

__device__ __forceinline__ float gelu_f(float x){
    return 0.5f*x*(1.0f + erff(x*0.70710678118654752440f));
}
__device__ __forceinline__ float tf32r(float x){ return wmma::__float_to_tf32(x); }

__device__ __forceinline__ void cpa16(void* dst, const void* src){
    unsigned d = (unsigned)__cvta_generic_to_shared(dst);
    asm volatile("cp.async.cg.shared.global [%0], [%1], 16;\n" :: "r"(d), "l"(src));
}
__device__ __forceinline__ void cp_commit(){ asm volatile("cp.async.commit_group;\n"); }
template<int NG> __device__ __forceinline__ void cp_wait(){ asm volatile("cp.async.wait_group %0;\n" :: "n"(NG)); }

// block reduce over NW warps (NW <= 16)
template<int NW>
__device__ __forceinline__ float block_reduce_sum(float v, float* red){
    int tid = threadIdx.x;
    #pragma unroll
    for (int o=16;o;o>>=1) v += __shfl_xor_sync(0xffffffffu, v, o);
    if ((tid&31)==0) red[tid>>5] = v;
    __syncthreads();
    if (tid < 32) {
        float r = (tid < NW) ? red[tid] : 0.0f;
        #pragma unroll
        for (int o=8;o;o>>=1) r += __shfl_xor_sync(0xffffffffu, r, o);
        if (tid==0) red[0] = r;
    }
    __syncthreads();
    float out = red[0];
    __syncthreads();
    return out;
}

// ---------------- item mask ----------------
__global__ void mask_kernel(const float* __restrict__ x, float* __restrict__ mask){
    int row = blockIdx.x*8 + (threadIdx.x>>5);
    int lane = threadIdx.x & 31;
    float4 v = reinterpret_cast<const float4*>(x + (long)row*DIN)[lane];
    bool nz = (v.x!=0.0f)||(v.y!=0.0f)||(v.z!=0.0f)||(v.w!=0.0f);
    unsigned b = __ballot_sync(0xffffffffu, nz);
    if (lane==0) mask[row] = b ? 1.0f : 0.0f;
}

// ---------------- convert fp32 -> tf32(RN)-rounded fp32 ----------------
__global__ void cvt_tf32_kernel(const float* __restrict__ in, float* __restrict__ out, int n4){
    int t = blockIdx.x*256 + threadIdx.x;
    if (t >= n4) return;
    float4 v = ((const float4*)in)[t];
    v.x = tf32r(v.x); v.y = tf32r(v.y); v.z = tf32r(v.z); v.w = tf32r(v.w);
    ((float4*)out)[t] = v;
}

// ---------------- pack Wq|Wk|Wv into [128][1536], tf32-rounded ----------------
__global__ void pack_qkv_kernel(const float* __restrict__ Wq, const float* __restrict__ Wk,
                                const float* __restrict__ Wv, float* __restrict__ W){
    int t = blockIdx.x*256 + threadIdx.x;
    int r = t >> 7, c4 = t & 127;
    const float4* q4 = (const float4*)Wq;
    const float4* k4 = (const float4*)Wk;
    const float4* v4 = (const float4*)Wv;
    float4* w4 = (float4*)W;
    float4 a = q4[r*128 + c4], b = k4[r*128 + c4], c = v4[r*128 + c4];
    a.x=tf32r(a.x); a.y=tf32r(a.y); a.z=tf32r(a.z); a.w=tf32r(a.w);
    b.x=tf32r(b.x); b.y=tf32r(b.y); b.z=tf32r(b.z); b.w=tf32r(b.w);
    c.x=tf32r(c.x); c.y=tf32r(c.y); c.z=tf32r(c.z); c.w=tf32r(c.w);
    w4[r*384 + c4      ] = a;
    w4[r*384 + 128 + c4] = b;
    w4[r*384 + 256 + c4] = c;
}

// ---------------- cp.async double-buffered WMMA-tf32 GEMM ----------------
// Inputs MUST already be tf32-rounded in memory. Outputs are tf32-rounded.
// Block tile 128x64, 8 warps (4x2), warp tile 32x32, K-chunk 32.
__global__ __launch_bounds__(256) void gemm_ca(
    const float* __restrict__ A, const float* __restrict__ B, float* __restrict__ C,
    int N, int K, int epi, const float* __restrict__ mask)
{
    extern __shared__ float sm[];
    float* As0 = sm;                 // 128 x PAs
    float* As1 = sm + 128*PAs;
    float* Bs0 = sm + 2*128*PAs;     // 32 x PBs
    float* Bs1 = Bs0 + 32*PBs;
    float* Cs  = sm;                 // epilogue reuse
    int tid = threadIdx.x;
    int warp = tid >> 5;
    int wr = warp >> 1, wc = warp & 1;
    int row0 = blockIdx.y*128, col0 = blockIdx.x*64;

    wmma::fragment<wmma::accumulator, 16, 16, 8, float> acc[2][2];
    #pragma unroll
    for (int i=0;i<2;i++)
        #pragma unroll
        for (int j=0;j<2;j++) wmma::fill_fragment(acc[i][j], 0.0f);

    auto loadA = [&](float* dst, int k0){
        #pragma unroll
        for (int t=0;t<4;t++){
            int idx = tid + t*256;
            int m = idx>>3, kg = idx&7;
            cpa16(dst + m*PAs + kg*4, A + (long)(row0+m)*K + k0 + kg*4);
        }
    };
    auto loadB = [&](float* dst, int k0){
        #pragma unroll
        for (int t=0;t<2;t++){
            int idx = tid + t*256;
            int kk = idx>>4, ng = idx&15;
            cpa16(dst + kk*PBs + ng*4, B + (long)(k0+kk)*N + col0 + ng*4);
        }
    };

    int nch = K >> 5;
    loadA(As0, 0); loadB(Bs0, 0); cp_commit();
    for (int c=0; c<nch; c++){
        if (c+1 < nch){
            float* da = (c&1) ? As0 : As1;
            float* db = (c&1) ? Bs0 : Bs1;
            loadA(da, (c+1)*32); loadB(db, (c+1)*32); cp_commit();
            cp_wait<1>();
        } else {
            cp_wait<0>();
        }
        __syncthreads();
        float* Asb = (c&1) ? As1 : As0;
        float* Bsb = (c&1) ? Bs1 : Bs0;
        #pragma unroll
        for (int ks=0; ks<4; ks++){
            wmma::fragment<wmma::matrix_a, 16, 16, 8, wmma::precision::tf32, wmma::row_major> a0, a1;
            wmma::fragment<wmma::matrix_b, 16, 16, 8, wmma::precision::tf32, wmma::row_major> b0, b1;
            wmma::load_matrix_sync(a0, Asb + (wr*32    )*PAs + ks*8, PAs);
            wmma::load_matrix_sync(a1, Asb + (wr*32+16 )*PAs + ks*8, PAs);
            wmma::load_matrix_sync(b0, Bsb + (ks*8)*PBs + wc*32,      PBs);
            wmma::load_matrix_sync(b1, Bsb + (ks*8)*PBs + wc*32 + 16, PBs);
            wmma::mma_sync(acc[0][0], a0, b0, acc[0][0]);
            wmma::mma_sync(acc[0][1], a0, b1, acc[0][1]);
            wmma::mma_sync(acc[1][0], a1, b0, acc[1][0]);
            wmma::mma_sync(acc[1][1], a1, b1, acc[1][1]);
        }
        __syncthreads();
    }

    #pragma unroll
    for (int i=0;i<2;i++)
        #pragma unroll
        for (int j=0;j<2;j++)
            wmma::store_matrix_sync(Cs + (wr*32+i*16)*PCs + wc*32 + j*16, acc[i][j], PCs, wmma::mem_row_major);
    __syncthreads();
    #pragma unroll
    for (int t=0;t<8;t++){
        int idx = tid + t*256;
        int m = idx>>4, ng = idx&15;
        int r = row0 + m;
        const float* p = Cs + m*PCs + ng*4;
        float4 outv;
        if (epi==1){
            float mrow = mask[r];
            outv.x = tf32r(gelu_f(p[0])*mrow); outv.y = tf32r(gelu_f(p[1])*mrow);
            outv.z = tf32r(gelu_f(p[2])*mrow); outv.w = tf32r(gelu_f(p[3])*mrow);
        } else {
            outv.x = tf32r(p[0]); outv.y = tf32r(p[1]);
            outv.z = tf32r(p[2]); outv.w = tf32r(p[3]);
        }
        *(float4*)(C + (long)r*N + col0 + ng*4) = outv;
    }
}

// ---------------- attention per (head, set): WMMA-tf32 matmuls ----------------
// qkv already tf32-rounded; P rounded at softmax write; output rounded.
__global__ __launch_bounds__(256) void attn_wmma(
    const float* __restrict__ qkv, float* __restrict__ o)
{
    int h = blockIdx.x, s = blockIdx.y;
    extern __shared__ float sm[];
    float* qs = sm;
    float* ks = sm + 128*PT;
    float* vs = sm + 2*128*PT;
    int tid = threadIdx.x;
    int warp = tid >> 5, lane = tid & 31;
    int wr = warp >> 1, wc = warp & 1;
    long base = (long)(s*M_ITEMS)*QKVW + h*DH;

    for (int idx=tid; idx<128*32; idx+=256){
        int m = idx>>5, dg = idx&31;
        const float* rowp = qkv + base + (long)m*QKVW + dg*4;
        float4 a = *(const float4*)(rowp);
        float4 b = *(const float4*)(rowp + 512);
        float4 c = *(const float4*)(rowp + 1024);
        *(float4*)(qs + m*PT + dg*4) = a;
        *(float4*)(ks + m*PT + dg*4) = b;
        *(float4*)(vs + m*PT + dg*4) = c;
    }
    __syncthreads();

    const float scale = 0.08838834764831844f;  // 1/sqrt(128)

    // S = Q @ K^T * scale
    {
        wmma::fragment<wmma::accumulator, 16, 16, 8, float> acc[2][4];
        #pragma unroll
        for (int i=0;i<2;i++)
            #pragma unroll
            for (int t=0;t<4;t++) wmma::fill_fragment(acc[i][t], 0.0f);
        #pragma unroll
        for (int k8=0; k8<16; k8++){
            wmma::fragment<wmma::matrix_a, 16, 16, 8, wmma::precision::tf32, wmma::row_major> a0, a1;
            wmma::load_matrix_sync(a0, qs + (wr*32    )*PT + k8*8, PT);
            wmma::load_matrix_sync(a1, qs + (wr*32+16 )*PT + k8*8, PT);
            #pragma unroll
            for (int t=0;t<4;t++){
                wmma::fragment<wmma::matrix_b, 16, 16, 8, wmma::precision::tf32, wmma::col_major> bf;
                wmma::load_matrix_sync(bf, ks + (wc*64 + t*16)*PT + k8*8, PT);
                wmma::mma_sync(acc[0][t], a0, bf, acc[0][t]);
                wmma::mma_sync(acc[1][t], a1, bf, acc[1][t]);
            }
        }
        __syncthreads();
        #pragma unroll
        for (int i=0;i<2;i++)
            #pragma unroll
            for (int t=0;t<4;t++){
                #pragma unroll
                for (int e=0;e<acc[i][t].num_elements;e++) acc[i][t].x[e] *= scale;
                wmma::store_matrix_sync(qs + (wr*32+i*16)*PT + wc*64 + t*16, acc[i][t], PT, wmma::mem_row_major);
            }
        __syncthreads();
    }

    // masked softmax (fp32), write P as tf32-RN
    for (int m=warp; m<128; m+=8){
        float* row = qs + m*PT;
        float vals[4]; float mx = -INFINITY;
        #pragma unroll
        for (int r=0;r<4;r++){ vals[r] = row[lane+32*r]; mx = fmaxf(mx, vals[r]); }
        #pragma unroll
        for (int off=16;off;off>>=1) mx = fmaxf(mx, __shfl_xor_sync(0xffffffffu, mx, off));
        float sum = 0.0f;
        #pragma unroll
        for (int r=0;r<4;r++){
            float e = (vals[r]!=0.0f) ? expf(vals[r]-mx) : 0.0f;
            vals[r] = e; sum += e;
        }
        #pragma unroll
        for (int off=16;off;off>>=1) sum += __shfl_xor_sync(0xffffffffu, sum, off);
        float inv = 1.0f/(sum + 1e-10f);
        #pragma unroll
        for (int r=0;r<4;r++) row[lane+32*r] = tf32r(vals[r]*inv);
    }
    __syncthreads();

    // O = P @ V, rounded output to global
    {
        long obase = (long)(s*M_ITEMS)*HD + h*DH;
        wmma::fragment<wmma::accumulator, 16, 16, 8, float> acc[2][4];
        #pragma unroll
        for (int i=0;i<2;i++)
            #pragma unroll
            for (int t=0;t<4;t++) wmma::fill_fragment(acc[i][t], 0.0f);
        #pragma unroll
        for (int k8=0; k8<16; k8++){
            wmma::fragment<wmma::matrix_a, 16, 16, 8, wmma::precision::tf32, wmma::row_major> a0, a1;
            wmma::load_matrix_sync(a0, qs + (wr*32    )*PT + k8*8, PT);
            wmma::load_matrix_sync(a1, qs + (wr*32+16 )*PT + k8*8, PT);
            #pragma unroll
            for (int t=0;t<4;t++){
                wmma::fragment<wmma::matrix_b, 16, 16, 8, wmma::precision::tf32, wmma::row_major> bf;
                wmma::load_matrix_sync(bf, vs + (k8*8)*PT + wc*64 + t*16, PT);
                wmma::mma_sync(acc[0][t], a0, bf, acc[0][t]);
                wmma::mma_sync(acc[1][t], a1, bf, acc[1][t]);
            }
        }
        #pragma unroll
        for (int i=0;i<2;i++)
            #pragma unroll
            for (int t=0;t<4;t++){
                #pragma unroll
                for (int e=0;e<acc[i][t].num_elements;e++) acc[i][t].x[e] = tf32r(acc[i][t].x[e]);
                wmma::store_matrix_sync(o + obase + (long)(wr*32+i*16)*HD + wc*64 + t*16, acc[i][t], HD, wmma::mem_row_major);
            }
    }
}

// ---------------- set_norm (512 threads), outputs tf32-rounded ----------------
__global__ __launch_bounds__(512) void setnorm_kernel(
    float* __restrict__ hbuf, const float* __restrict__ abuf,
    const float* __restrict__ mitem, const int* __restrict__ x_size,
    int apply_gelu)
{
    int s = blockIdx.x;
    extern __shared__ float sm[];
    float* ts = sm;              // [128][130]
    float* rs = sm + 128*130;    // [128]
    __shared__ float red[32];
    int tid = threadIdx.x;
    long base = (long)s*M_ITEMS*DM;

    for (int idx=tid; idx<128*32; idx+=512){
        int m = idx>>5, dg = idx&31;
        float mrow = mitem[s*M_ITEMS+m];
        float4 hv = *(const float4*)(hbuf + base + (long)m*DM + dg*4);
        float4 av = *(const float4*)(abuf + base + (long)m*DM + dg*4);
        float a0 = apply_gelu ? gelu_f(av.x) : av.x;
        float a1 = apply_gelu ? gelu_f(av.y) : av.y;
        float a2 = apply_gelu ? gelu_f(av.z) : av.z;
        float a3 = apply_gelu ? gelu_f(av.w) : av.w;
        float* pt = ts + m*130 + dg*4;
        pt[0] = hv.x + a0*mrow; pt[1] = hv.y + a1*mrow;
        pt[2] = hv.z + a2*mrow; pt[3] = hv.w + a3*mrow;
    }
    __syncthreads();

    int warp = tid>>5, lane = tid&31;
    for (int m=warp; m<128; m+=16){
        float v = ts[m*130+lane] + ts[m*130+lane+32] + ts[m*130+lane+64] + ts[m*130+lane+96];
        #pragma unroll
        for (int off=16;off;off>>=1) v += __shfl_xor_sync(0xffffffffu, v, off);
        if (lane==0) rs[m] = v;
    }
    __syncthreads();

    float tv = (tid<128) ? rs[tid] : 0.0f;
    float total = block_reduce_sum<16>(tv, red);
    int szi = x_size[s]; if (szi < 1) szi = 1;
    float denom = (float)szi * 128.0f;
    float mean = total / denom;

    float vv = 0.0f;
    for (int idx=tid; idx<128*32; idx+=512){
        int m = idx>>5, dg = idx&31;
        if (rs[m] != 0.0f){
            float* pt = ts + m*130 + dg*4;
            float d0 = pt[0]-mean, d1 = pt[1]-mean, d2 = pt[2]-mean, d3 = pt[3]-mean;
            vv += d0*d0 + d1*d1 + d2*d2 + d3*d3;
        }
    }
    float vart = block_reduce_sum<16>(vv, red);
    float inv = 1.0f/(sqrtf(vart/denom) + 1e-8f);

    for (int idx=tid; idx<128*32; idx+=512){
        int m = idx>>5, dg = idx&31;
        float mr = (rs[m] != 0.0f) ? 1.0f : 0.0f;
        float* pt = ts + m*130 + dg*4;
        float4 outv;
        outv.x = tf32r((pt[0]-mean)*inv*mr);
        outv.y = tf32r((pt[1]-mean)*inv*mr);
        outv.z = tf32r((pt[2]-mean)*inv*mr);
        outv.w = tf32r((pt[3]-mean)*inv*mr);
        *(float4*)(hbuf + base + (long)m*DM + dg*4) = outv;
    }
}

// ---------------- cross-set Gram via WMMA bf16 ----------------
__global__ __launch_bounds__(256) void gram_bf16_kernel(
    const float* __restrict__ z, float* __restrict__ Bout)
{
    int h = blockIdx.y;
    int p = blockIdx.x;
    int j = 0, rem = p;
    while (rem >= S_SETS - j){ rem -= S_SETS - j; j++; }
    int i = j + rem;

    extern __shared__ __nv_bfloat16 smb[];
    __nv_bfloat16* zj = smb;
    __nv_bfloat16* zi = smb + 128*PZ;
    __shared__ float red[32];
    int tid = threadIdx.x;
    int warp = tid >> 5;
    int wr = warp >> 1, wc = warp & 1;
    long basej = (long)(j*M_ITEMS)*HD + h*DH;
    long basei = (long)(i*M_ITEMS)*HD + h*DH;

    for (int idx=tid; idx<128*32; idx+=256){
        int m = idx>>5, dg = idx&31;
        float4 a = *(const float4*)(z + basej + (long)m*HD + dg*4);
        float4 b = *(const float4*)(z + basei + (long)m*HD + dg*4);
        __nv_bfloat162* pa = (__nv_bfloat162*)(zj + m*PZ + dg*4);
        pa[0] = __floats2bfloat162_rn(a.x, a.y);
        pa[1] = __floats2bfloat162_rn(a.z, a.w);
        __nv_bfloat162* pb = (__nv_bfloat162*)(zi + m*PZ + dg*4);
        pb[0] = __floats2bfloat162_rn(b.x, b.y);
        pb[1] = __floats2bfloat162_rn(b.z, b.w);
    }
    __syncthreads();

    wmma::fragment<wmma::accumulator, 16, 16, 16, float> acc[2][4];
    #pragma unroll
    for (int a=0;a<2;a++)
        #pragma unroll
        for (int t=0;t<4;t++) wmma::fill_fragment(acc[a][t], 0.0f);

    #pragma unroll
    for (int ks=0; ks<8; ks++){
        wmma::fragment<wmma::matrix_a, 16, 16, 16, __nv_bfloat16, wmma::row_major> a0, a1;
        wmma::load_matrix_sync(a0, zj + (wr*32    )*PZ + ks*16, PZ);
        wmma::load_matrix_sync(a1, zj + (wr*32+16 )*PZ + ks*16, PZ);
        #pragma unroll
        for (int t=0;t<4;t++){
            wmma::fragment<wmma::matrix_b, 16, 16, 16, __nv_bfloat16, wmma::col_major> bfrag;
            wmma::load_matrix_sync(bfrag, zi + (wc*64 + t*16)*PZ + ks*16, PZ);
            wmma::mma_sync(acc[0][t], a0, bfrag, acc[0][t]);
            wmma::mma_sync(acc[1][t], a1, bfrag, acc[1][t]);
        }
    }

    const float scale = 0.08838834764831844f;
    float lsum = 0.0f;
    #pragma unroll
    for (int a=0;a<2;a++)
        #pragma unroll
        for (int t=0;t<4;t++)
            #pragma unroll
            for (int e=0;e<acc[a][t].num_elements;e++){
                float vv = acc[a][t].x[e]*scale;
                lsum += (vv >= 0.0f) ? vv : 0.3f*vv;
            }
    float total = block_reduce_sum<8>(lsum, red);
    if (tid==0){
        Bout[(j*S_SETS+i)*H_HEADS + h] = total;
        Bout[(i*S_SETS+j)*H_HEADS + h] = total;
    }
}

// ---------------- finalize ----------------
__global__ void final_kernel(const float* __restrict__ Bm, const int* __restrict__ x_size,
                             const float* __restrict__ w2, float* __restrict__ out)
{
    int idx = blockIdx.x*256 + threadIdx.x;
    if (idx >= S_SETS*S_SETS) return;
    int j = idx / S_SETS, i = idx % S_SETS;
    int szi = x_size[i]; if (szi < 1) szi = 1;
    float acc = 0.0f;
    #pragma unroll
    for (int h=0; h<H_HEADS; h++) acc += Bm[(j*S_SETS+i)*H_HEADS + h] * w2[h];
    out[idx] = acc / (float)szi / (float)M_ITEMS;
}

// ---------------- launch ----------------
extern "C" void kernel_launch(void* const* d_in, const int* in_sizes, int n_in,
                              void* d_out, int out_size)
{
    const float* x      = (const float*)d_in[0];
    const int*   x_size = (const int*)  d_in[1];
    const float* W_proj = (const float*)d_in[2];
    const float* Wq     = (const float*)d_in[3];
    const float* Wk     = (const float*)d_in[4];
    const float* Wv     = (const float*)d_in[5];
    const float* Wh     = (const float*)d_in[6];
    const float* Wfc    = (const float*)d_in[7];
    const float* Wc     = (const float*)d_in[8];
    const float* w2     = (const float*)d_in[9];
    float* out = (float*)d_out;

    float *pm, *px, *ph, *pqkv, *pwproj, *pwqkv, *pwh, *pwfc, *pwc, *po, *pt, *pz, *pB;
    cudaGetSymbolAddress((void**)&pm, g_mask);
    cudaGetSymbolAddress((void**)&px, g_x);
    cudaGetSymbolAddress((void**)&ph, g_h);
    cudaGetSymbolAddress((void**)&pqkv, g_qkv);
    cudaGetSymbolAddress((void**)&pwproj, g_wproj);
    cudaGetSymbolAddress((void**)&pwqkv, g_wqkv);
    cudaGetSymbolAddress((void**)&pwh, g_wh);
    cudaGetSymbolAddress((void**)&pwfc, g_wfc);
    cudaGetSymbolAddress((void**)&pwc, g_wc);
    cudaGetSymbolAddress((void**)&po, g_o);
    cudaGetSymbolAddress((void**)&pt, g_t);
    cudaGetSymbolAddress((void**)&pz, g_z);
    cudaGetSymbolAddress((void**)&pB, g_B);

    const int GEMM_SMEM = (2*128*PAs + 2*32*PBs)*4;   // 54272 B
    const int ATTN_SMEM = 3*128*PT*4;                 // 202752 B
    const int GRAM_SMEM = 2*128*PZ*2;                 //  69632 B
    const int SN_SMEM   = 128*130*4 + 128*4;          //  67072 B
    cudaFuncSetAttribute(gemm_ca,          cudaFuncAttributeMaxDynamicSharedMemorySize, GEMM_SMEM);
    cudaFuncSetAttribute(attn_wmma,        cudaFuncAttributeMaxDynamicSharedMemorySize, ATTN_SMEM);
    cudaFuncSetAttribute(gram_bf16_kernel, cudaFuncAttributeMaxDynamicSharedMemorySize, GRAM_SMEM);
    cudaFuncSetAttribute(setnorm_kernel,   cudaFuncAttributeMaxDynamicSharedMemorySize, SN_SMEM);

    // prep: mask + tf32-rounded copies of x and all weights
    mask_kernel<<<ROWS/8, 256>>>(x, pm);
    cvt_tf32_kernel<<<(ROWS*DIN/4 + 255)/256, 256>>>(x, px, ROWS*DIN/4);
    cvt_tf32_kernel<<<(DIN*DM/4 + 255)/256, 256>>>(W_proj, pwproj, DIN*DM/4);
    for (int l=0; l<L_LAYERS; l++)
        pack_qkv_kernel<<<64, 256>>>(Wq + (long)l*DM*HD, Wk + (long)l*DM*HD, Wv + (long)l*DM*HD,
                                     pwqkv + (long)l*DM*QKVW);
    cvt_tf32_kernel<<<(L_LAYERS*HD*DM/4 + 255)/256, 256>>>(Wh, pwh, L_LAYERS*HD*DM/4);
    cvt_tf32_kernel<<<(L_LAYERS*DM*DM/4 + 255)/256, 256>>>(Wfc, pwfc, L_LAYERS*DM*DM/4);
    cvt_tf32_kernel<<<(DM*HD/4 + 255)/256, 256>>>(Wc, pwc, DM*HD/4);

    gemm_ca<<<dim3(DM/64, ROWS/128), 256, GEMM_SMEM>>>(px, pwproj, ph, DM, DIN, 1, pm);

    for (int l=0; l<L_LAYERS; l++){
        gemm_ca<<<dim3(QKVW/64, ROWS/128), 256, GEMM_SMEM>>>(ph, pwqkv + (long)l*DM*QKVW, pqkv, QKVW, DM, 0, nullptr);
        attn_wmma<<<dim3(H_HEADS, S_SETS), 256, ATTN_SMEM>>>(pqkv, po);
        gemm_ca<<<dim3(DM/64, ROWS/128), 256, GEMM_SMEM>>>(po, pwh + (long)l*HD*DM, pt, DM, HD, 0, nullptr);
        setnorm_kernel<<<S_SETS, 512, SN_SMEM>>>(ph, pt, pm, x_size, 0);
        gemm_ca<<<dim3(DM/64, ROWS/128), 256, GEMM_SMEM>>>(ph, pwfc + (long)l*DM*DM, pt, DM, DM, 0, nullptr);
        setnorm_kernel<<<S_SETS, 512, SN_SMEM>>>(ph, pt, pm, x_size, 1);
    }

    gemm_ca<<<dim3(HD/64, ROWS/128), 256, GEMM_SMEM>>>(ph, pwc, pz, HD, DM, 0, nullptr);
    gram_bf16_kernel<<<dim3(S_SETS*(S_SETS+1)/2, H_HEADS), 256, GRAM_SMEM>>>(pz, pB);
    final_kernel<<<(S_SETS*S_SETS + 255)/256, 256>>>(pB, x_size, w2, out);
}

// round 12
// speedup vs baseline: 3.5107x; 1.0718x over previous
#include <cuda_runtime.h>
#include <cuda_bf16.h>
#include <math.h>
#include <mma.h>

using namespace nvcuda;

#define S_SETS 48
#define M_ITEMS 128
#define DIN 128
#define DM 128
#define H_HEADS 4
#define DH 128
#define L_LAYERS 2
#define ROWS (S_SETS*M_ITEMS)   /* 6144 */
#define HD (H_HEADS*DH)         /* 512  */
#define QKVW 1536

#define PAs 36   /* gemm A-tile pitch (floats) */
#define PT 132   /* attn smem pitch (floats) */
#define PZ 136   /* gram pitch (bf16) */

// ---------------- device scratch ----------------
__device__ float g_mask[ROWS];
__device__ float g_x[ROWS*DIN];
__device__ float g_h[ROWS*DM];
__device__ float g_qkv[ROWS*QKVW];
__device__ float g_wproj[DIN*DM];
__device__ float g_wqkv[L_LAYERS*DM*QKVW];
__device__ float g_wh[L_LAYERS*HD*DM];
__device__ float g_wfc[L_LAYERS*DM*DM];
__device__ float g_wc[DM*HD];
__device__ float g_o[ROWS*HD];
__device__ float g_t[ROWS*DM];
__device__ __nv_bfloat16 g_z[ROWS*HD];
__device__ float g_B[S_SETS*S_SETS*H_HEADS];

__device__ __forceinline__ float gelu_f(float x){
    return 0.5f*x*(1.0f + erff(x*0.70710678118654752440f));
}
__device__ __forceinline__ float tf32r(float x){ return wmma::__float_to_tf32(x); }

__device__ __forceinline__ void cpa16(void* dst, const void* src){
    unsigned d = (unsigned)__cvta_generic_to_shared(dst);
    asm volatile("cp.async.cg.shared.global [%0], [%1], 16;\n" :: "r"(d), "l"(src));
}
__device__ __forceinline__ void cp_commit(){ asm volatile("cp.async.commit_group;\n"); }
template<int NG> __device__ __forceinline__ void cp_wait(){ asm volatile("cp.async.wait_group %0;\n" :: "n"(NG)); }

template<int NW>
__device__ __forceinline__ float block_reduce_sum(float v, float* red){
    int tid = threadIdx.x;
    #pragma unroll
    for (int o=16;o;o>>=1) v += __shfl_xor_sync(0xffffffffu, v, o);
    if ((tid&31)==0) red[tid>>5] = v;
    __syncthreads();
    if (tid < 32) {
        float r = (tid < NW) ? red[tid] : 0.0f;
        #pragma unroll
        for (int o=8;o;o>>=1) r += __shfl_xor_sync(0xffffffffu, r, o);
        if (tid==0) red[0] = r;
    }
    __syncthreads();
    float out = red[0];
    __syncthreads();
    return out;
}

// ---------------- item mask ----------------
__global__ void mask_kernel(const float* __restrict__ x, float* __restrict__ mask){
    int row = blockIdx.x*8 + (threadIdx.x>>5);
    int lane = threadIdx.x & 31;
    float4 v = reinterpret_cast<const float4*>(x + (long)row*DIN)[lane];
    bool nz = (v.x!=0.0f)||(v.y!=0.0f)||(v.z!=0.0f)||(v.w!=0.0f);
    unsigned b = __ballot_sync(0xffffffffu, nz);
    if (lane==0) mask[row] = b ? 1.0f : 0.0f;
}

// ---------------- fused prep: tf32-round x + all weights, pack qkv ----------------
// segment sizes (float4 groups): x 196608 | wproj 4096 | wh 32768 | wfc 8192 | wc 16384 | qkv 98304
__global__ void prep_kernel(
    const float* __restrict__ x, const float* __restrict__ wproj,
    const float* __restrict__ wh, const float* __restrict__ wfc, const float* __restrict__ wc,
    const float* __restrict__ Wq, const float* __restrict__ Wk, const float* __restrict__ Wv,
    float* __restrict__ ox, float* __restrict__ owproj, float* __restrict__ owh,
    float* __restrict__ owfc, float* __restrict__ owc, float* __restrict__ owqkv)
{
    int g = blockIdx.x*256 + threadIdx.x;
    if (g >= 356352) return;
    const float* src; float* dst;
    if (g < 196608){ src = x + (long)g*4; dst = ox + (long)g*4; }
    else if (g < 200704){ int o=g-196608; src=wproj+(long)o*4; dst=owproj+(long)o*4; }
    else if (g < 233472){ int o=g-200704; src=wh+(long)o*4;    dst=owh+(long)o*4; }
    else if (g < 241664){ int o=g-233472; src=wfc+(long)o*4;   dst=owfc+(long)o*4; }
    else if (g < 258048){ int o=g-241664; src=wc+(long)o*4;    dst=owc+(long)o*4; }
    else {
        int o = g-258048;
        int l = o / 49152, r2 = o % 49152;
        int r = r2 / 384, c4 = r2 % 384;
        int q = c4 >> 7, cq = c4 & 127;
        const float* s3 = (q==0)?Wq:(q==1)?Wk:Wv;
        src = s3 + (long)l*65536 + r*512 + cq*4;
        dst = owqkv + (long)l*196608 + r*1536 + q*512 + cq*4;
    }
    float4 v = *(const float4*)src;
    v.x=tf32r(v.x); v.y=tf32r(v.y); v.z=tf32r(v.z); v.w=tf32r(v.w);
    *(float4*)dst = v;
}

// ---------------- cp.async double-buffered WMMA-tf32 GEMM, templated BN ----------------
// Block tile 128xBN, 8 warps (4x2), warp tile 32x(BN/2). K-chunk 32.
template<int BN>
__global__ __launch_bounds__(256) void gemm_ca(
    const float* __restrict__ A, const float* __restrict__ B,
    float* __restrict__ C32, __nv_bfloat16* __restrict__ C16,
    int N, int K, int epi, const float* __restrict__ mask)
{
    constexpr int PB_ = BN + 4;
    constexpr int PC_ = BN + 4;
    constexpr int F4R = BN/4;
    constexpr int NF  = BN/32;
    extern __shared__ float sm[];
    float* As0 = sm;
    float* As1 = sm + 128*PAs;
    float* Bs0 = sm + 2*128*PAs;
    float* Bs1 = Bs0 + 32*PB_;
    float* Cs  = sm;
    int tid = threadIdx.x;
    int warp = tid >> 5;
    int wr = warp >> 1, wc = warp & 1;
    int row0 = blockIdx.y*128, col0 = blockIdx.x*BN;

    wmma::fragment<wmma::accumulator, 16, 16, 8, float> acc[2][NF];
    #pragma unroll
    for (int i=0;i<2;i++)
        #pragma unroll
        for (int t=0;t<NF;t++) wmma::fill_fragment(acc[i][t], 0.0f);

    auto loadA = [&](float* dst, int k0){
        #pragma unroll
        for (int t=0;t<4;t++){
            int idx = tid + t*256;
            int m = idx>>3, kg = idx&7;
            cpa16(dst + m*PAs + kg*4, A + (long)(row0+m)*K + k0 + kg*4);
        }
    };
    auto loadB = [&](float* dst, int k0){
        #pragma unroll
        for (int t=0;t<BN/32;t++){
            int idx = tid + t*256;
            int kk = idx / F4R, ng = idx % F4R;
            cpa16(dst + kk*PB_ + ng*4, B + (long)(k0+kk)*N + col0 + ng*4);
        }
    };

    int nch = K >> 5;
    loadA(As0, 0); loadB(Bs0, 0); cp_commit();
    for (int c=0; c<nch; c++){
        if (c+1 < nch){
            float* da = (c&1) ? As0 : As1;
            float* db = (c&1) ? Bs0 : Bs1;
            loadA(da, (c+1)*32); loadB(db, (c+1)*32); cp_commit();
            cp_wait<1>();
        } else {
            cp_wait<0>();
        }
        __syncthreads();
        float* Asb = (c&1) ? As1 : As0;
        float* Bsb = (c&1) ? Bs1 : Bs0;
        #pragma unroll
        for (int ks=0; ks<4; ks++){
            wmma::fragment<wmma::matrix_a, 16, 16, 8, wmma::precision::tf32, wmma::row_major> a0, a1;
            wmma::load_matrix_sync(a0, Asb + (wr*32    )*PAs + ks*8, PAs);
            wmma::load_matrix_sync(a1, Asb + (wr*32+16 )*PAs + ks*8, PAs);
            #pragma unroll
            for (int t=0;t<NF;t++){
                wmma::fragment<wmma::matrix_b, 16, 16, 8, wmma::precision::tf32, wmma::row_major> bf;
                wmma::load_matrix_sync(bf, Bsb + (ks*8)*PB_ + wc*(BN/2) + t*16, PB_);
                wmma::mma_sync(acc[0][t], a0, bf, acc[0][t]);
                wmma::mma_sync(acc[1][t], a1, bf, acc[1][t]);
            }
        }
        __syncthreads();
    }

    #pragma unroll
    for (int i=0;i<2;i++)
        #pragma unroll
        for (int t=0;t<NF;t++)
            wmma::store_matrix_sync(Cs + (wr*32+i*16)*PC_ + wc*(BN/2) + t*16, acc[i][t], PC_, wmma::mem_row_major);
    __syncthreads();
    #pragma unroll
    for (int t=0;t<BN/8;t++){
        int idx = tid + t*256;
        int m = idx / F4R, ng = idx % F4R;
        int r = row0 + m;
        const float* p = Cs + m*PC_ + ng*4;
        float v0=p[0], v1=p[1], v2=p[2], v3=p[3];
        if (epi==1){
            float mrow = mask[r];
            v0 = gelu_f(v0)*mrow; v1 = gelu_f(v1)*mrow;
            v2 = gelu_f(v2)*mrow; v3 = gelu_f(v3)*mrow;
        }
        long off = (long)r*N + col0 + ng*4;
        if (C32){
            float4 outv;
            outv.x = tf32r(v0); outv.y = tf32r(v1); outv.z = tf32r(v2); outv.w = tf32r(v3);
            *(float4*)(C32 + off) = outv;
        }
        if (C16){
            __nv_bfloat162* d = (__nv_bfloat162*)(C16 + off);
            d[0] = __floats2bfloat162_rn(v0, v1);
            d[1] = __floats2bfloat162_rn(v2, v3);
        }
    }
}

// ---------------- attention per (head, set): WMMA-tf32 matmuls ----------------
__global__ __launch_bounds__(256) void attn_wmma(
    const float* __restrict__ qkv, float* __restrict__ o)
{
    int h = blockIdx.x, s = blockIdx.y;
    extern __shared__ float sm[];
    float* qs = sm;
    float* ks = sm + 128*PT;
    float* vs = sm + 2*128*PT;
    int tid = threadIdx.x;
    int warp = tid >> 5, lane = tid & 31;
    int wr = warp >> 1, wc = warp & 1;
    long base = (long)(s*M_ITEMS)*QKVW + h*DH;

    for (int idx=tid; idx<128*32; idx+=256){
        int m = idx>>5, dg = idx&31;
        const float* rowp = qkv + base + (long)m*QKVW + dg*4;
        *(float4*)(qs + m*PT + dg*4) = *(const float4*)(rowp);
        *(float4*)(ks + m*PT + dg*4) = *(const float4*)(rowp + 512);
        *(float4*)(vs + m*PT + dg*4) = *(const float4*)(rowp + 1024);
    }
    __syncthreads();

    const float scale = 0.08838834764831844f;  // 1/sqrt(128)

    {
        wmma::fragment<wmma::accumulator, 16, 16, 8, float> acc[2][4];
        #pragma unroll
        for (int i=0;i<2;i++)
            #pragma unroll
            for (int t=0;t<4;t++) wmma::fill_fragment(acc[i][t], 0.0f);
        #pragma unroll
        for (int k8=0; k8<16; k8++){
            wmma::fragment<wmma::matrix_a, 16, 16, 8, wmma::precision::tf32, wmma::row_major> a0, a1;
            wmma::load_matrix_sync(a0, qs + (wr*32    )*PT + k8*8, PT);
            wmma::load_matrix_sync(a1, qs + (wr*32+16 )*PT + k8*8, PT);
            #pragma unroll
            for (int t=0;t<4;t++){
                wmma::fragment<wmma::matrix_b, 16, 16, 8, wmma::precision::tf32, wmma::col_major> bf;
                wmma::load_matrix_sync(bf, ks + (wc*64 + t*16)*PT + k8*8, PT);
                wmma::mma_sync(acc[0][t], a0, bf, acc[0][t]);
                wmma::mma_sync(acc[1][t], a1, bf, acc[1][t]);
            }
        }
        __syncthreads();
        #pragma unroll
        for (int i=0;i<2;i++)
            #pragma unroll
            for (int t=0;t<4;t++){
                #pragma unroll
                for (int e=0;e<acc[i][t].num_elements;e++) acc[i][t].x[e] *= scale;
                wmma::store_matrix_sync(qs + (wr*32+i*16)*PT + wc*64 + t*16, acc[i][t], PT, wmma::mem_row_major);
            }
        __syncthreads();
    }

    for (int m=warp; m<128; m+=8){
        float* row = qs + m*PT;
        float vals[4]; float mx = -INFINITY;
        #pragma unroll
        for (int r=0;r<4;r++){ vals[r] = row[lane+32*r]; mx = fmaxf(mx, vals[r]); }
        #pragma unroll
        for (int off=16;off;off>>=1) mx = fmaxf(mx, __shfl_xor_sync(0xffffffffu, mx, off));
        float sum = 0.0f;
        #pragma unroll
        for (int r=0;r<4;r++){
            float e = (vals[r]!=0.0f) ? expf(vals[r]-mx) : 0.0f;
            vals[r] = e; sum += e;
        }
        #pragma unroll
        for (int off=16;off;off>>=1) sum += __shfl_xor_sync(0xffffffffu, sum, off);
        float inv = 1.0f/(sum + 1e-10f);
        #pragma unroll
        for (int r=0;r<4;r++) row[lane+32*r] = tf32r(vals[r]*inv);
    }
    __syncthreads();

    {
        long obase = (long)(s*M_ITEMS)*HD + h*DH;
        wmma::fragment<wmma::accumulator, 16, 16, 8, float> acc[2][4];
        #pragma unroll
        for (int i=0;i<2;i++)
            #pragma unroll
            for (int t=0;t<4;t++) wmma::fill_fragment(acc[i][t], 0.0f);
        #pragma unroll
        for (int k8=0; k8<16; k8++){
            wmma::fragment<wmma::matrix_a, 16, 16, 8, wmma::precision::tf32, wmma::row_major> a0, a1;
            wmma::load_matrix_sync(a0, qs + (wr*32    )*PT + k8*8, PT);
            wmma::load_matrix_sync(a1, qs + (wr*32+16 )*PT + k8*8, PT);
            #pragma unroll
            for (int t=0;t<4;t++){
                wmma::fragment<wmma::matrix_b, 16, 16, 8, wmma::precision::tf32, wmma::row_major> bf;
                wmma::load_matrix_sync(bf, vs + (k8*8)*PT + wc*64 + t*16, PT);
                wmma::mma_sync(acc[0][t], a0, bf, acc[0][t]);
                wmma::mma_sync(acc[1][t], a1, bf, acc[1][t]);
            }
        }
        #pragma unroll
        for (int i=0;i<2;i++)
            #pragma unroll
            for (int t=0;t<4;t++){
                #pragma unroll
                for (int e=0;e<acc[i][t].num_elements;e++) acc[i][t].x[e] = tf32r(acc[i][t].x[e]);
                wmma::store_matrix_sync(o + obase + (long)(wr*32+i*16)*HD + wc*64 + t*16, acc[i][t], HD, wmma::mem_row_major);
            }
    }
}

// ---------------- set_norm (512 threads), outputs tf32-rounded ----------------
__global__ __launch_bounds__(512) void setnorm_kernel(
    float* __restrict__ hbuf, const float* __restrict__ abuf,
    const float* __restrict__ mitem, const int* __restrict__ x_size,
    int apply_gelu)
{
    int s = blockIdx.x;
    extern __shared__ float sm[];
    float* ts = sm;              // [128][130]
    __shared__ float rs[128];
    __shared__ float red[32];
    int tid = threadIdx.x;
    long base = (long)s*M_ITEMS*DM;

    for (int idx=tid; idx<128*32; idx+=512){
        int m = idx>>5, dg = idx&31;
        float mrow = mitem[s*M_ITEMS+m];
        float4 hv = *(const float4*)(hbuf + base + (long)m*DM + dg*4);
        float4 av = *(const float4*)(abuf + base + (long)m*DM + dg*4);
        float a0 = apply_gelu ? gelu_f(av.x) : av.x;
        float a1 = apply_gelu ? gelu_f(av.y) : av.y;
        float a2 = apply_gelu ? gelu_f(av.z) : av.z;
        float a3 = apply_gelu ? gelu_f(av.w) : av.w;
        float* pt = ts + m*130 + dg*4;
        pt[0] = hv.x + a0*mrow; pt[1] = hv.y + a1*mrow;
        pt[2] = hv.z + a2*mrow; pt[3] = hv.w + a3*mrow;
    }
    __syncthreads();

    int warp = tid>>5, lane = tid&31;
    for (int m=warp; m<128; m+=16){
        float v = ts[m*130+lane] + ts[m*130+lane+32] + ts[m*130+lane+64] + ts[m*130+lane+96];
        #pragma unroll
        for (int off=16;off;off>>=1) v += __shfl_xor_sync(0xffffffffu, v, off);
        if (lane==0) rs[m] = v;
    }
    __syncthreads();

    float tv = (tid<128) ? rs[tid] : 0.0f;
    float total = block_reduce_sum<16>(tv, red);
    int szi = x_size[s]; if (szi < 1) szi = 1;
    float denom = (float)szi * 128.0f;
    float mean = total / denom;

    float vv = 0.0f;
    for (int idx=tid; idx<128*32; idx+=512){
        int m = idx>>5, dg = idx&31;
        if (rs[m] != 0.0f){
            float* pt = ts + m*130 + dg*4;
            float d0 = pt[0]-mean, d1 = pt[1]-mean, d2 = pt[2]-mean, d3 = pt[3]-mean;
            vv += d0*d0 + d1*d1 + d2*d2 + d3*d3;
        }
    }
    float vart = block_reduce_sum<16>(vv, red);
    float inv = 1.0f/(sqrtf(vart/denom) + 1e-8f);

    for (int idx=tid; idx<128*32; idx+=512){
        int m = idx>>5, dg = idx&31;
        float mr = (rs[m] != 0.0f) ? 1.0f : 0.0f;
        float* pt = ts + m*130 + dg*4;
        float4 outv;
        outv.x = tf32r((pt[0]-mean)*inv*mr);
        outv.y = tf32r((pt[1]-mean)*inv*mr);
        outv.z = tf32r((pt[2]-mean)*inv*mr);
        outv.w = tf32r((pt[3]-mean)*inv*mr);
        *(float4*)(hbuf + base + (long)m*DM + dg*4) = outv;
    }
}

// ---------------- paired cross-set Gram via bf16 WMMA ----------------
// One block handles (j,i0) and (j,i1=i0+1) for one head, sharing the zj tile.
// 8 warps as 2x4; warp tile 64x64 (acc[4][4]).
__global__ __launch_bounds__(256) void gram_pair_kernel(
    const __nv_bfloat16* __restrict__ z, float* __restrict__ Bout)
{
    int h = blockIdx.y;
    int p = blockIdx.x;
    int j = 0;
    while (p >= ((49-j)>>1)){ p -= (49-j)>>1; j++; }
    int i0 = j + 2*p;
    int i1 = i0 + 1;
    bool has1 = (i1 < S_SETS);
    int i1c = has1 ? i1 : i0;

    extern __shared__ char smraw[];
    __nv_bfloat16* zj = (__nv_bfloat16*)smraw;          // [128][PZ]
    __nv_bfloat16* zi = zj + 128*PZ;                    // [256][PZ]
    __shared__ float wsum[8];
    int tid = threadIdx.x;
    int warp = tid >> 5, lane = tid & 31;
    int wr = warp >> 2;
    int wc = warp & 3;
    long basej  = (long)(j  *M_ITEMS)*HD + h*DH;
    long basei0 = (long)(i0 *M_ITEMS)*HD + h*DH;
    long basei1 = (long)(i1c*M_ITEMS)*HD + h*DH;

    for (int idx=tid; idx<128*16; idx+=256){
        int m = idx>>4, g = idx&15;
        *(uint4*)(zj + m*PZ + g*8)        = *(const uint4*)(z + basej  + (long)m*HD + g*8);
        *(uint4*)(zi + m*PZ + g*8)        = *(const uint4*)(z + basei0 + (long)m*HD + g*8);
        *(uint4*)(zi + (128+m)*PZ + g*8)  = *(const uint4*)(z + basei1 + (long)m*HD + g*8);
    }
    __syncthreads();

    wmma::fragment<wmma::accumulator, 16, 16, 16, float> acc[4][4];
    #pragma unroll
    for (int a=0;a<4;a++)
        #pragma unroll
        for (int t=0;t<4;t++) wmma::fill_fragment(acc[a][t], 0.0f);

    #pragma unroll
    for (int ks=0; ks<8; ks++){
        wmma::fragment<wmma::matrix_a, 16, 16, 16, __nv_bfloat16, wmma::row_major> af[4];
        #pragma unroll
        for (int a=0;a<4;a++)
            wmma::load_matrix_sync(af[a], zj + (wr*64 + a*16)*PZ + ks*16, PZ);
        #pragma unroll
        for (int t=0;t<4;t++){
            wmma::fragment<wmma::matrix_b, 16, 16, 16, __nv_bfloat16, wmma::col_major> bfrag;
            wmma::load_matrix_sync(bfrag, zi + (wc*64 + t*16)*PZ + ks*16, PZ);
            #pragma unroll
            for (int a=0;a<4;a++)
                wmma::mma_sync(acc[a][t], af[a], bfrag, acc[a][t]);
        }
    }

    const float scale = 0.08838834764831844f;
    float lsum = 0.0f;
    #pragma unroll
    for (int a=0;a<4;a++)
        #pragma unroll
        for (int t=0;t<4;t++)
            #pragma unroll
            for (int e=0;e<acc[a][t].num_elements;e++){
                float vv = acc[a][t].x[e]*scale;
                lsum += (vv >= 0.0f) ? vv : 0.3f*vv;
            }
    #pragma unroll
    for (int o=16;o;o>>=1) lsum += __shfl_xor_sync(0xffffffffu, lsum, o);
    if (lane==0) wsum[warp] = lsum;
    __syncthreads();
    if (tid==0){
        float s0 = wsum[0]+wsum[1]+wsum[4]+wsum[5];
        float s1 = wsum[2]+wsum[3]+wsum[6]+wsum[7];
        Bout[(j*S_SETS+i0)*H_HEADS + h] = s0;
        Bout[(i0*S_SETS+j)*H_HEADS + h] = s0;
        if (has1){
            Bout[(j*S_SETS+i1)*H_HEADS + h] = s1;
            Bout[(i1*S_SETS+j)*H_HEADS + h] = s1;
        }
    }
}

// ---------------- finalize ----------------
__global__ void final_kernel(const float* __restrict__ Bm, const int* __restrict__ x_size,
                             const float* __restrict__ w2, float* __restrict__ out)
{
    int idx = blockIdx.x*256 + threadIdx.x;
    if (idx >= S_SETS*S_SETS) return;
    int j = idx / S_SETS, i = idx % S_SETS;
    int szi = x_size[i]; if (szi < 1) szi = 1;
    float acc = 0.0f;
    #pragma unroll
    for (int h=0; h<H_HEADS; h++) acc += Bm[(j*S_SETS+i)*H_HEADS + h] * w2[h];
    out[idx] = acc / (float)szi / (float)M_ITEMS;
}

// ---------------- launch ----------------
extern "C" void kernel_launch(void* const* d_in, const int* in_sizes, int n_in,
                              void* d_out, int out_size)
{
    const float* x      = (const float*)d_in[0];
    const int*   x_size = (const int*)  d_in[1];
    const float* W_proj = (const float*)d_in[2];
    const float* Wq     = (const float*)d_in[3];
    const float* Wk     = (const float*)d_in[4];
    const float* Wv     = (const float*)d_in[5];
    const float* Wh     = (const float*)d_in[6];
    const float* Wfc    = (const float*)d_in[7];
    const float* Wc     = (const float*)d_in[8];
    const float* w2     = (const float*)d_in[9];
    float* out = (float*)d_out;

    float *pm, *px, *ph, *pqkv, *pwproj, *pwqkv, *pwh, *pwfc, *pwc, *po, *pt, *pB;
    __nv_bfloat16 *pz;
    cudaGetSymbolAddress((void**)&pm, g_mask);
    cudaGetSymbolAddress((void**)&px, g_x);
    cudaGetSymbolAddress((void**)&ph, g_h);
    cudaGetSymbolAddress((void**)&pqkv, g_qkv);
    cudaGetSymbolAddress((void**)&pwproj, g_wproj);
    cudaGetSymbolAddress((void**)&pwqkv, g_wqkv);
    cudaGetSymbolAddress((void**)&pwh, g_wh);
    cudaGetSymbolAddress((void**)&pwfc, g_wfc);
    cudaGetSymbolAddress((void**)&pwc, g_wc);
    cudaGetSymbolAddress((void**)&po, g_o);
    cudaGetSymbolAddress((void**)&pt, g_t);
    cudaGetSymbolAddress((void**)&pz, g_z);
    cudaGetSymbolAddress((void**)&pB, g_B);

    const int GEMM64_SMEM  = (2*128*PAs + 2*32*68)*4;    // 54272 B
    const int GEMM128_SMEM = (2*128*PAs + 2*32*132)*4;   // 70656 B
    const int ATTN_SMEM    = 3*128*PT*4;                 // 202752 B
    const int GRAM_SMEM    = 384*PZ*2;                   // 104448 B
    const int SN_SMEM      = 128*130*4;                  // 66560 B
    cudaFuncSetAttribute(gemm_ca<64>,      cudaFuncAttributeMaxDynamicSharedMemorySize, GEMM64_SMEM);
    cudaFuncSetAttribute(gemm_ca<128>,     cudaFuncAttributeMaxDynamicSharedMemorySize, GEMM128_SMEM);
    cudaFuncSetAttribute(attn_wmma,        cudaFuncAttributeMaxDynamicSharedMemorySize, ATTN_SMEM);
    cudaFuncSetAttribute(gram_pair_kernel, cudaFuncAttributeMaxDynamicSharedMemorySize, GRAM_SMEM);
    cudaFuncSetAttribute(setnorm_kernel,   cudaFuncAttributeMaxDynamicSharedMemorySize, SN_SMEM);

    mask_kernel<<<ROWS/8, 256>>>(x, pm);
    prep_kernel<<<1392, 256>>>(x, W_proj, Wh, Wfc, Wc, Wq, Wk, Wv,
                               px, pwproj, pwh, pwfc, pwc, pwqkv);

    gemm_ca<64><<<dim3(2, 48), 256, GEMM64_SMEM>>>(px, pwproj, ph, nullptr, DM, DIN, 1, pm);

    for (int l=0; l<L_LAYERS; l++){
        gemm_ca<128><<<dim3(12, 48), 256, GEMM128_SMEM>>>(ph, pwqkv + (long)l*DM*QKVW, pqkv, nullptr, QKVW, DM, 0, nullptr);
        attn_wmma<<<dim3(H_HEADS, S_SETS), 256, ATTN_SMEM>>>(pqkv, po);
        gemm_ca<64><<<dim3(2, 48), 256, GEMM64_SMEM>>>(po, pwh + (long)l*HD*DM, pt, nullptr, DM, HD, 0, nullptr);
        setnorm_kernel<<<S_SETS, 512, SN_SMEM>>>(ph, pt, pm, x_size, 0);
        gemm_ca<64><<<dim3(2, 48), 256, GEMM64_SMEM>>>(ph, pwfc + (long)l*DM*DM, pt, nullptr, DM, DM, 0, nullptr);
        setnorm_kernel<<<S_SETS, 512, SN_SMEM>>>(ph, pt, pm, x_size, 1);
    }

    gemm_ca<128><<<dim3(4, 48), 256, GEMM128_SMEM>>>(ph, pwc, nullptr, pz, HD, DM, 0, nullptr);
    gram_pair_kernel<<<dim3(600, H_HEADS), 256, GRAM_SMEM>>>(pz, pB);
    final_kernel<<<(S_SETS*S_SETS + 255)/256, 256>>>(pB, x_size, w2, out);
}